// round 3
// baseline (speedup 1.0000x reference)
#include <cuda_runtime.h>
#include <math.h>

// Problem constants
#define B_   4
#define N_   2048
#define D_   1024
#define H_   16
#define HD_  64
#define E3_  192          // 3 * head_dim, chunk order (k, q, v)
#define MROWS (B_ * N_)   // 8192

#define NEG_INF (-1e30f)

// Scratch (allocation-free rule: __device__ globals)
__device__ float g_kqv[(size_t)B_ * H_ * N_ * E3_];  // [b][h][n][e]  ~100 MB
__device__ float g_sa [(size_t)B_ * N_ * D_];        // [b][n][h*hd+d] ~33 MB

// ---------------------------------------------------------------------------
// QKV projection: per head h, C[8192 x 192] = X[8192 x 1024] @ W_h[1024 x 192] + b_h
// Tile 64x64x16, 256 threads, 4x4 micro-tiles.
// ---------------------------------------------------------------------------
__global__ __launch_bounds__(256) void qkv_gemm_kernel(
    const float* __restrict__ X, const float* __restrict__ W,
    const float* __restrict__ bias)
{
    __shared__ float As[16][64];   // A transposed: As[k][m]
    __shared__ float Bs[16][64];   // Bs[k][n]

    const int h  = blockIdx.z;
    const int m0 = blockIdx.x * 64;
    const int n0 = blockIdx.y * 64;
    const float* Wh = W + (size_t)h * (D_ * E3_);

    const int tid  = threadIdx.x;
    const int ty   = tid >> 4, tx = tid & 15;
    const int arow = tid >> 2;            // 0..63
    const int akc  = (tid & 3) << 2;      // 0,4,8,12
    const int bkr  = tid >> 4;            // 0..15
    const int bcol = (tid & 15) << 2;     // 0..60

    float acc[4][4] = {};

    for (int k0 = 0; k0 < D_; k0 += 16) {
        float4 av = *(const float4*)(X + (size_t)(m0 + arow) * D_ + k0 + akc);
        As[akc + 0][arow] = av.x;
        As[akc + 1][arow] = av.y;
        As[akc + 2][arow] = av.z;
        As[akc + 3][arow] = av.w;
        *(float4*)(&Bs[bkr][bcol]) =
            *(const float4*)(Wh + (size_t)(k0 + bkr) * E3_ + n0 + bcol);
        __syncthreads();
#pragma unroll
        for (int k = 0; k < 16; ++k) {
            float4 a4 = *(const float4*)&As[k][ty << 2];
            float4 b4 = *(const float4*)&Bs[k][tx << 2];
            float a[4] = {a4.x, a4.y, a4.z, a4.w};
            float b[4] = {b4.x, b4.y, b4.z, b4.w};
#pragma unroll
            for (int i = 0; i < 4; ++i)
#pragma unroll
                for (int j = 0; j < 4; ++j)
                    acc[i][j] = fmaf(a[i], b[j], acc[i][j]);
        }
        __syncthreads();
    }

#pragma unroll
    for (int i = 0; i < 4; ++i) {
        int m = m0 + (ty << 2) + i;
        int b = m / N_, n = m - b * N_;
        int e = n0 + (tx << 2);
        float4 o;
        o.x = acc[i][0] + bias[h * E3_ + e + 0];
        o.y = acc[i][1] + bias[h * E3_ + e + 1];
        o.z = acc[i][2] + bias[h * E3_ + e + 2];
        o.w = acc[i][3] + bias[h * E3_ + e + 3];
        *(float4*)(g_kqv + (((size_t)b * H_ + h) * N_ + n) * E3_ + e) = o;
    }
}

// ---------------------------------------------------------------------------
// Causal flash attention: one block = 64 queries of one (b,h). Online softmax.
// Skips fully-masked key tiles (kt > qi): ~2x work saving.
// Smem: Qs (Q^T) + KP (K^T, reused for P) + Vs = exactly 48 KB.
// ---------------------------------------------------------------------------
__global__ __launch_bounds__(256) void attn_kernel()
{
    __shared__ float Qs[64][64];  // [d][r], pre-scaled by 1/sqrt(hd)
    __shared__ float KP[64][64];  // phase 1: K^T [d][c]; phase 2: P [r][c]
    __shared__ float Vs[64][64];  // [c][d]

    const int qi  = blockIdx.x;
    const int h   = blockIdx.y;
    const int b   = blockIdx.z;
    const int tid = threadIdx.x;
    const int ty  = tid >> 4, tx = tid & 15;
    const int lr  = tid >> 2;          // 0..63 (row being loaded)
    const int ld0 = (tid & 3) << 4;    // 0,16,32,48 (dim offset)

    const size_t base  = ((size_t)b * H_ + h) * N_ * E3_;
    const int    qbase = qi * 64;

    // Load Q tile transposed, folding in 1/sqrt(64) = 0.125
    {
        const float* qp = g_kqv + base + (size_t)(qbase + lr) * E3_ + HD_; // q chunk
#pragma unroll
        for (int u = 0; u < 4; ++u) {
            int d = ld0 + (u << 2);
            float4 v = *(const float4*)(qp + d);
            Qs[d + 0][lr] = v.x * 0.125f;
            Qs[d + 1][lr] = v.y * 0.125f;
            Qs[d + 2][lr] = v.z * 0.125f;
            Qs[d + 3][lr] = v.w * 0.125f;
        }
    }

    float acc[4][4] = {};
    float mrow[4] = {NEG_INF, NEG_INF, NEG_INF, NEG_INF};
    float lrow[4] = {};

    for (int kt = 0; kt <= qi; ++kt) {
        __syncthreads();  // previous iteration done reading KP/Vs; Q store visible
        // Load K^T and V for this key tile
        {
            const int kbase = kt * 64;
            const float* kp = g_kqv + base + (size_t)(kbase + lr) * E3_;      // k chunk
            const float* vp = kp + 2 * HD_;                                   // v chunk
#pragma unroll
            for (int u = 0; u < 4; ++u) {
                int d = ld0 + (u << 2);
                float4 kv = *(const float4*)(kp + d);
                KP[d + 0][lr] = kv.x;
                KP[d + 1][lr] = kv.y;
                KP[d + 2][lr] = kv.z;
                KP[d + 3][lr] = kv.w;
                *(float4*)&Vs[lr][d] = *(const float4*)(vp + d);
            }
        }
        __syncthreads();

        // S = (Q/8) K^T  : 4x4 micro-tile per thread
        float s[4][4] = {};
#pragma unroll 8
        for (int k = 0; k < 64; ++k) {
            float4 a4 = *(const float4*)&Qs[k][ty << 2];
            float4 b4 = *(const float4*)&KP[k][tx << 2];
            float a[4]  = {a4.x, a4.y, a4.z, a4.w};
            float bb[4] = {b4.x, b4.y, b4.z, b4.w};
#pragma unroll
            for (int i = 0; i < 4; ++i)
#pragma unroll
                for (int j = 0; j < 4; ++j)
                    s[i][j] = fmaf(a[i], bb[j], s[i][j]);
        }

        // Causal mask (only the diagonal tile has masked entries)
        if (kt == qi) {
#pragma unroll
            for (int i = 0; i < 4; ++i) {
                int qg = (ty << 2) + i;
#pragma unroll
                for (int j = 0; j < 4; ++j)
                    if (((tx << 2) + j) > qg) s[i][j] = NEG_INF;
            }
        }

        // Online softmax update (row reductions via shfl over the 16 tx lanes)
        float p[4][4];
        float alpha[4];
#pragma unroll
        for (int i = 0; i < 4; ++i) {
            float mx = fmaxf(fmaxf(s[i][0], s[i][1]), fmaxf(s[i][2], s[i][3]));
#pragma unroll
            for (int o = 8; o > 0; o >>= 1)
                mx = fmaxf(mx, __shfl_xor_sync(0xffffffffu, mx, o));
            float mnew = fmaxf(mrow[i], mx);
            float a_ = __expf(mrow[i] - mnew);
            float sum = 0.f;
#pragma unroll
            for (int j = 0; j < 4; ++j) {
                float e = __expf(s[i][j] - mnew);
                p[i][j] = e;
                sum += e;
            }
#pragma unroll
            for (int o = 8; o > 0; o >>= 1)
                sum += __shfl_xor_sync(0xffffffffu, sum, o);
            lrow[i]  = lrow[i] * a_ + sum;
            mrow[i]  = mnew;
            alpha[i] = a_;
        }
#pragma unroll
        for (int i = 0; i < 4; ++i)
#pragma unroll
            for (int j = 0; j < 4; ++j) acc[i][j] *= alpha[i];

        __syncthreads();  // everyone done reading KP as K
        // Store P into KP buffer, layout [r][c]
#pragma unroll
        for (int i = 0; i < 4; ++i)
            *(float4*)&KP[(ty << 2) + i][tx << 2] =
                make_float4(p[i][0], p[i][1], p[i][2], p[i][3]);
        __syncthreads();

        // O += P @ V
        for (int c0 = 0; c0 < 64; c0 += 4) {
            float pr[4][4];
#pragma unroll
            for (int i = 0; i < 4; ++i) {
                float4 t = *(const float4*)&KP[(ty << 2) + i][c0];
                pr[i][0] = t.x; pr[i][1] = t.y; pr[i][2] = t.z; pr[i][3] = t.w;
            }
#pragma unroll
            for (int cc = 0; cc < 4; ++cc) {
                float4 v4 = *(const float4*)&Vs[c0 + cc][tx << 2];
                float vv[4] = {v4.x, v4.y, v4.z, v4.w};
#pragma unroll
                for (int i = 0; i < 4; ++i)
#pragma unroll
                    for (int j = 0; j < 4; ++j)
                        acc[i][j] = fmaf(pr[i][cc], vv[j], acc[i][j]);
            }
        }
    }

    // Normalize and write to g_sa with heads concatenated along feature dim
#pragma unroll
    for (int i = 0; i < 4; ++i) {
        float inv = 1.0f / lrow[i];
        int n = qbase + (ty << 2) + i;
        float4 o = make_float4(acc[i][0] * inv, acc[i][1] * inv,
                               acc[i][2] * inv, acc[i][3] * inv);
        *(float4*)(g_sa + ((size_t)b * N_ + n) * D_ + h * HD_ + (tx << 2)) = o;
    }
}

// ---------------------------------------------------------------------------
// Output projection: out[8192 x 1024] = g_sa @ W_proj + b_proj
// ---------------------------------------------------------------------------
__global__ __launch_bounds__(256) void proj_gemm_kernel(
    const float* __restrict__ W, const float* __restrict__ bias,
    float* __restrict__ out)
{
    __shared__ float As[16][64];
    __shared__ float Bs[16][64];

    const int m0 = blockIdx.x * 64;
    const int n0 = blockIdx.y * 64;

    const int tid  = threadIdx.x;
    const int ty   = tid >> 4, tx = tid & 15;
    const int arow = tid >> 2;
    const int akc  = (tid & 3) << 2;
    const int bkr  = tid >> 4;
    const int bcol = (tid & 15) << 2;

    float acc[4][4] = {};

    for (int k0 = 0; k0 < D_; k0 += 16) {
        float4 av = *(const float4*)(g_sa + (size_t)(m0 + arow) * D_ + k0 + akc);
        As[akc + 0][arow] = av.x;
        As[akc + 1][arow] = av.y;
        As[akc + 2][arow] = av.z;
        As[akc + 3][arow] = av.w;
        *(float4*)(&Bs[bkr][bcol]) =
            *(const float4*)(W + (size_t)(k0 + bkr) * D_ + n0 + bcol);
        __syncthreads();
#pragma unroll
        for (int k = 0; k < 16; ++k) {
            float4 a4 = *(const float4*)&As[k][ty << 2];
            float4 b4 = *(const float4*)&Bs[k][tx << 2];
            float a[4] = {a4.x, a4.y, a4.z, a4.w};
            float b[4] = {b4.x, b4.y, b4.z, b4.w};
#pragma unroll
            for (int i = 0; i < 4; ++i)
#pragma unroll
                for (int j = 0; j < 4; ++j)
                    acc[i][j] = fmaf(a[i], b[j], acc[i][j]);
        }
        __syncthreads();
    }

#pragma unroll
    for (int i = 0; i < 4; ++i) {
        int m = m0 + (ty << 2) + i;
        int e = n0 + (tx << 2);
        float4 o;
        o.x = acc[i][0] + bias[e + 0];
        o.y = acc[i][1] + bias[e + 1];
        o.z = acc[i][2] + bias[e + 2];
        o.w = acc[i][3] + bias[e + 3];
        *(float4*)(out + (size_t)m * D_ + e) = o;
    }
}

// ---------------------------------------------------------------------------
extern "C" void kernel_launch(void* const* d_in, const int* in_sizes, int n_in,
                              void* d_out, int out_size)
{
    const float* x      = (const float*)d_in[0];
    const float* W_kqv  = (const float*)d_in[1];
    const float* b_kqv  = (const float*)d_in[2];
    const float* W_proj = (const float*)d_in[3];
    const float* b_proj = (const float*)d_in[4];
    float* out = (float*)d_out;

    qkv_gemm_kernel<<<dim3(MROWS / 64, E3_ / 64, H_), 256>>>(x, W_kqv, b_kqv);
    attn_kernel<<<dim3(N_ / 64, H_, B_), 256>>>();
    proj_gemm_kernel<<<dim3(MROWS / 64, D_ / 64), 256>>>(W_proj, b_proj, out);
}

// round 5
// speedup vs baseline: 1.8106x; 1.8106x over previous
#include <cuda_runtime.h>
#include <cstdint>
#include <math.h>

// Problem constants
#define B_   4
#define N_   2048
#define D_   1024
#define H_   16
#define HD_  64
#define E3_  192          // 3 * head_dim, chunk order (k, q, v)
#define MROWS (B_ * N_)   // 8192

#define NEG_INF (-1e30f)

// Scratch (allocation-free rule: __device__ globals)
__device__ float g_kqv[(size_t)B_ * H_ * N_ * E3_];   // [b][h][n][e]
__device__ float g_sa [(size_t)B_ * N_ * D_];         // [b][n][h*hd+d] (tf32-rounded)
__device__ float g_xt [(size_t)MROWS * D_];           // x, tf32-rounded
__device__ float g_wt_kqv[(size_t)H_ * E3_ * D_];     // W_kqv^T [h][e][k], tf32-rounded
__device__ float g_wt_proj[(size_t)D_ * D_];          // W_proj^T [n][k], tf32-rounded

// ---------------------------------------------------------------------------
// Helpers
// ---------------------------------------------------------------------------
__device__ __forceinline__ float rtf(float x) {   // round-to-nearest tf32
    uint32_t u;
    asm("cvt.rna.tf32.f32 %0, %1;" : "=r"(u) : "f"(x));
    return __uint_as_float(u);
}
__device__ __forceinline__ void cpa16(uint32_t dst, const void* src) {
    asm volatile("cp.async.ca.shared.global [%0], [%1], 16;" :: "r"(dst), "l"(src));
}
__device__ __forceinline__ uint32_t smem_u32(const void* p) {
    uint32_t a;
    asm("{ .reg .u64 t; cvta.to.shared.u64 t, %1; cvt.u32.u64 %0, t; }"
        : "=r"(a) : "l"(p));
    return a;
}
__device__ __forceinline__ void mma_tf32(float* c, const uint32_t* a, const uint32_t* b) {
    asm volatile(
        "mma.sync.aligned.m16n8k8.row.col.f32.tf32.tf32.f32 "
        "{%0,%1,%2,%3}, {%4,%5,%6,%7}, {%8,%9}, {%0,%1,%2,%3};"
        : "+f"(c[0]), "+f"(c[1]), "+f"(c[2]), "+f"(c[3])
        : "r"(a[0]), "r"(a[1]), "r"(a[2]), "r"(a[3]), "r"(b[0]), "r"(b[1]));
}

// ---------------------------------------------------------------------------
// Prep kernels: tf32-round x; transpose+round weights to [n][k]
// ---------------------------------------------------------------------------
__global__ void rtf_x_kernel(const float* __restrict__ x) {
    size_t i = ((size_t)blockIdx.x * 256 + threadIdx.x) * 4;
    float4 v = *(const float4*)(x + i);
    v.x = rtf(v.x); v.y = rtf(v.y); v.z = rtf(v.z); v.w = rtf(v.w);
    *(float4*)(g_xt + i) = v;
}

__global__ void tr_kqv_kernel(const float* __restrict__ W) {
    __shared__ float t[32][33];
    const int h = blockIdx.z, k0 = blockIdx.x * 32, e0 = blockIdx.y * 32;
    const float* Wh = W + (size_t)h * D_ * E3_;
    float* Wt = g_wt_kqv + (size_t)h * E3_ * D_;
    const int x = threadIdx.x, y = threadIdx.y;
#pragma unroll
    for (int j = 0; j < 32; j += 8)
        t[y + j][x] = Wh[(size_t)(k0 + y + j) * E3_ + e0 + x];
    __syncthreads();
#pragma unroll
    for (int j = 0; j < 32; j += 8)
        Wt[(size_t)(e0 + y + j) * D_ + k0 + x] = rtf(t[x][y + j]);
}

__global__ void tr_proj_kernel(const float* __restrict__ W) {
    __shared__ float t[32][33];
    const int k0 = blockIdx.x * 32, n0 = blockIdx.y * 32;
    const int x = threadIdx.x, y = threadIdx.y;
#pragma unroll
    for (int j = 0; j < 32; j += 8)
        t[y + j][x] = W[(size_t)(k0 + y + j) * D_ + n0 + x];
    __syncthreads();
#pragma unroll
    for (int j = 0; j < 32; j += 8)
        g_wt_proj[(size_t)(n0 + y + j) * D_ + k0 + x] = rtf(t[x][y + j]);
}

// ---------------------------------------------------------------------------
// tf32 mma.sync GEMM. CTA tile 128 x NT, K=1024 in chunks of 32.
// 8 warps (2 M x 4 N), warp tile 64 x (NT/4), mma m16n8k8, f32 accumulate.
// cp.async double-buffered smem, padded stride 36 (conflict-free frag loads).
// PER_HEAD=1: A=g_xt, B=g_wt_kqv[head], C=g_kqv per-head layout, NT=192.
// PER_HEAD=0: A=g_sa, B=g_wt_proj,      C=Cout [8192x1024],      NT=128.
// ---------------------------------------------------------------------------
template <int NT, int PER_HEAD>
__global__ __launch_bounds__(256, 1) void gemm_mma_kernel(
    const float* __restrict__ bias, float* __restrict__ Cout)
{
    constexpr int NSUB = NT / 32;          // 8-wide n-subtiles per warp
    constexpr int AST = 128 * 36;          // floats per A stage
    constexpr int BST = NT * 36;
    extern __shared__ float sm[];
    float* As = sm;                        // [2][AST]
    float* Bs = sm + 2 * AST;              // [2][BST]

    const int tid  = threadIdx.x;
    const int m0   = blockIdx.x * 128;
    const int head = blockIdx.y;
    const int n0   = PER_HEAD ? 0 : blockIdx.y * NT;

    const float* Ab = (PER_HEAD ? g_xt : g_sa) + (size_t)m0 * D_;
    const float* Bt = PER_HEAD ? (g_wt_kqv + (size_t)head * E3_ * D_)
                               : (g_wt_proj + (size_t)n0 * D_);

    const uint32_t sA = smem_u32(As);
    const uint32_t sB = smem_u32(Bs);

    auto load_stage = [&](int kc, int buf) {
        const float* ap = Ab + kc * 32;
        const uint32_t da = sA + (uint32_t)buf * AST * 4;
#pragma unroll
        for (int j = 0; j < 4; ++j) {
            const int idx = tid + j * 256;
            const int r = idx >> 3, q = (idx & 7) << 2;
            cpa16(da + (uint32_t)(r * 36 + q) * 4, ap + (size_t)r * D_ + q);
        }
        const float* bp = Bt + kc * 32;
        const uint32_t db = sB + (uint32_t)buf * BST * 4;
#pragma unroll
        for (int j = 0; j < NT / 32; ++j) {
            const int idx = tid + j * 256;
            const int r = idx >> 3, q = (idx & 7) << 2;
            cpa16(db + (uint32_t)(r * 36 + q) * 4, bp + (size_t)r * D_ + q);
        }
        asm volatile("cp.async.commit_group;" ::: "memory");
    };

    const int w    = tid >> 5, lane = tid & 31;
    const int wm   = (w & 1) * 64;
    const int wn   = (w >> 1) * NSUB * 8;
    const int grp  = lane >> 2, tig = lane & 3;

    float acc[4][NSUB][4];
#pragma unroll
    for (int mi = 0; mi < 4; ++mi)
#pragma unroll
        for (int ni = 0; ni < NSUB; ++ni)
#pragma unroll
            for (int r = 0; r < 4; ++r) acc[mi][ni][r] = 0.f;

    load_stage(0, 0);
    load_stage(1, 1);

    for (int kc = 0; kc < 32; ++kc) {
        if (kc < 31) asm volatile("cp.async.wait_group 1;" ::: "memory");
        else         asm volatile("cp.async.wait_group 0;" ::: "memory");
        __syncthreads();
        const float* Ap = As + (kc & 1) * AST;
        const float* Bp = Bs + (kc & 1) * BST;
#pragma unroll
        for (int ks = 0; ks < 4; ++ks) {
            const int k = ks * 8;
            uint32_t a[4][4], bf[NSUB][2];
#pragma unroll
            for (int mi = 0; mi < 4; ++mi) {
                const float* p = Ap + (wm + mi * 16 + grp) * 36 + k + tig;
                a[mi][0] = __float_as_uint(p[0]);
                a[mi][1] = __float_as_uint(p[8 * 36]);
                a[mi][2] = __float_as_uint(p[4]);
                a[mi][3] = __float_as_uint(p[8 * 36 + 4]);
            }
#pragma unroll
            for (int ni = 0; ni < NSUB; ++ni) {
                const float* p = Bp + (wn + ni * 8 + grp) * 36 + k + tig;
                bf[ni][0] = __float_as_uint(p[0]);
                bf[ni][1] = __float_as_uint(p[4]);
            }
#pragma unroll
            for (int mi = 0; mi < 4; ++mi)
#pragma unroll
                for (int ni = 0; ni < NSUB; ++ni)
                    mma_tf32(acc[mi][ni], a[mi], bf[ni]);
        }
        __syncthreads();
        if (kc + 2 < 32) load_stage(kc + 2, kc & 1);
    }

    // Epilogue: c0,c1 -> row grp; c2,c3 -> row grp+8; cols 2*tig, 2*tig+1
#pragma unroll
    for (int mi = 0; mi < 4; ++mi) {
        const int mbase = m0 + wm + mi * 16 + grp;
#pragma unroll
        for (int half = 0; half < 2; ++half) {
            const int m = mbase + half * 8;
            float* dst;
            const float* bsp;
            if (PER_HEAD) {
                const int b = m >> 11, tok = m & 2047;
                dst = g_kqv + (((size_t)b * H_ + head) * N_ + tok) * E3_;
                bsp = bias + head * E3_;
            } else {
                dst = Cout + (size_t)m * D_ + n0;
                bsp = bias + n0;
            }
#pragma unroll
            for (int ni = 0; ni < NSUB; ++ni) {
                const int c = wn + ni * 8 + 2 * tig;
                float2 o;
                o.x = acc[mi][ni][half * 2 + 0] + bsp[c];
                o.y = acc[mi][ni][half * 2 + 1] + bsp[c + 1];
                *(float2*)(dst + c) = o;
            }
        }
    }
}

// ---------------------------------------------------------------------------
// Causal flash attention (fp32 SIMT; g_sa store is tf32-rounded for proj GEMM)
// ---------------------------------------------------------------------------
__global__ __launch_bounds__(256) void attn_kernel()
{
    __shared__ float Qs[64][64];
    __shared__ float KP[64][64];
    __shared__ float Vs[64][64];

    const int qi  = blockIdx.x;
    const int h   = blockIdx.y;
    const int b   = blockIdx.z;
    const int tid = threadIdx.x;
    const int ty  = tid >> 4, tx = tid & 15;
    const int lr  = tid >> 2;
    const int ld0 = (tid & 3) << 4;

    const size_t base  = ((size_t)b * H_ + h) * N_ * E3_;
    const int    qbase = qi * 64;

    {
        const float* qp = g_kqv + base + (size_t)(qbase + lr) * E3_ + HD_;
#pragma unroll
        for (int u = 0; u < 4; ++u) {
            int d = ld0 + (u << 2);
            float4 v = *(const float4*)(qp + d);
            Qs[d + 0][lr] = v.x * 0.125f;
            Qs[d + 1][lr] = v.y * 0.125f;
            Qs[d + 2][lr] = v.z * 0.125f;
            Qs[d + 3][lr] = v.w * 0.125f;
        }
    }

    float acc[4][4] = {};
    float mrow[4] = {NEG_INF, NEG_INF, NEG_INF, NEG_INF};
    float lrow[4] = {};

    for (int kt = 0; kt <= qi; ++kt) {
        __syncthreads();
        {
            const int kbase = kt * 64;
            const float* kp = g_kqv + base + (size_t)(kbase + lr) * E3_;
            const float* vp = kp + 2 * HD_;
#pragma unroll
            for (int u = 0; u < 4; ++u) {
                int d = ld0 + (u << 2);
                float4 kv = *(const float4*)(kp + d);
                KP[d + 0][lr] = kv.x;
                KP[d + 1][lr] = kv.y;
                KP[d + 2][lr] = kv.z;
                KP[d + 3][lr] = kv.w;
                *(float4*)&Vs[lr][d] = *(const float4*)(vp + d);
            }
        }
        __syncthreads();

        float s[4][4] = {};
#pragma unroll 8
        for (int k = 0; k < 64; ++k) {
            float4 a4 = *(const float4*)&Qs[k][ty << 2];
            float4 b4 = *(const float4*)&KP[k][tx << 2];
            float a[4]  = {a4.x, a4.y, a4.z, a4.w};
            float bb[4] = {b4.x, b4.y, b4.z, b4.w};
#pragma unroll
            for (int i = 0; i < 4; ++i)
#pragma unroll
                for (int j = 0; j < 4; ++j)
                    s[i][j] = fmaf(a[i], bb[j], s[i][j]);
        }

        if (kt == qi) {
#pragma unroll
            for (int i = 0; i < 4; ++i) {
                int qg = (ty << 2) + i;
#pragma unroll
                for (int j = 0; j < 4; ++j)
                    if (((tx << 2) + j) > qg) s[i][j] = NEG_INF;
            }
        }

        float p[4][4];
        float alpha[4];
#pragma unroll
        for (int i = 0; i < 4; ++i) {
            float mx = fmaxf(fmaxf(s[i][0], s[i][1]), fmaxf(s[i][2], s[i][3]));
#pragma unroll
            for (int o = 8; o > 0; o >>= 1)
                mx = fmaxf(mx, __shfl_xor_sync(0xffffffffu, mx, o));
            float mnew = fmaxf(mrow[i], mx);
            float a_ = __expf(mrow[i] - mnew);
            float sum = 0.f;
#pragma unroll
            for (int j = 0; j < 4; ++j) {
                float e = __expf(s[i][j] - mnew);
                p[i][j] = e;
                sum += e;
            }
#pragma unroll
            for (int o = 8; o > 0; o >>= 1)
                sum += __shfl_xor_sync(0xffffffffu, sum, o);
            lrow[i]  = lrow[i] * a_ + sum;
            mrow[i]  = mnew;
            alpha[i] = a_;
        }
#pragma unroll
        for (int i = 0; i < 4; ++i)
#pragma unroll
            for (int j = 0; j < 4; ++j) acc[i][j] *= alpha[i];

        __syncthreads();
#pragma unroll
        for (int i = 0; i < 4; ++i)
            *(float4*)&KP[(ty << 2) + i][tx << 2] =
                make_float4(p[i][0], p[i][1], p[i][2], p[i][3]);
        __syncthreads();

        for (int c0 = 0; c0 < 64; c0 += 4) {
            float pr[4][4];
#pragma unroll
            for (int i = 0; i < 4; ++i) {
                float4 t = *(const float4*)&KP[(ty << 2) + i][c0];
                pr[i][0] = t.x; pr[i][1] = t.y; pr[i][2] = t.z; pr[i][3] = t.w;
            }
#pragma unroll
            for (int cc = 0; cc < 4; ++cc) {
                float4 v4 = *(const float4*)&Vs[c0 + cc][tx << 2];
                float vv[4] = {v4.x, v4.y, v4.z, v4.w};
#pragma unroll
                for (int i = 0; i < 4; ++i)
#pragma unroll
                    for (int j = 0; j < 4; ++j)
                        acc[i][j] = fmaf(pr[i][cc], vv[j], acc[i][j]);
            }
        }
    }

#pragma unroll
    for (int i = 0; i < 4; ++i) {
        float inv = 1.0f / lrow[i];
        int n = qbase + (ty << 2) + i;
        float4 o = make_float4(rtf(acc[i][0] * inv), rtf(acc[i][1] * inv),
                               rtf(acc[i][2] * inv), rtf(acc[i][3] * inv));
        *(float4*)(g_sa + ((size_t)b * N_ + n) * D_ + h * HD_ + (tx << 2)) = o;
    }
}

// ---------------------------------------------------------------------------
extern "C" void kernel_launch(void* const* d_in, const int* in_sizes, int n_in,
                              void* d_out, int out_size)
{
    const float* x      = (const float*)d_in[0];
    const float* W_kqv  = (const float*)d_in[1];
    const float* b_kqv  = (const float*)d_in[2];
    const float* W_proj = (const float*)d_in[3];
    const float* b_proj = (const float*)d_in[4];
    float* out = (float*)d_out;

    const int SMEM_Q = (2 * 128 * 36 + 2 * E3_ * 36) * 4;   // 92160
    const int SMEM_P = (2 * 128 * 36 + 2 * 128 * 36) * 4;   // 73728
    cudaFuncSetAttribute(gemm_mma_kernel<E3_, 1>,
                         cudaFuncAttributeMaxDynamicSharedMemorySize, SMEM_Q);
    cudaFuncSetAttribute(gemm_mma_kernel<128, 0>,
                         cudaFuncAttributeMaxDynamicSharedMemorySize, SMEM_P);

    rtf_x_kernel<<<MROWS * D_ / 1024, 256>>>(x);
    tr_kqv_kernel<<<dim3(D_ / 32, E3_ / 32, H_), dim3(32, 8)>>>(W_kqv);
    tr_proj_kernel<<<dim3(D_ / 32, D_ / 32), dim3(32, 8)>>>(W_proj);

    gemm_mma_kernel<E3_, 1><<<dim3(MROWS / 128, H_), 256, SMEM_Q>>>(b_kqv, nullptr);
    attn_kernel<<<dim3(N_ / 64, H_, B_), 256>>>();
    gemm_mma_kernel<128, 0><<<dim3(MROWS / 128, D_ / 128), 256, SMEM_P>>>(b_proj, out);
}

// round 6
// speedup vs baseline: 2.8289x; 1.5624x over previous
#include <cuda_runtime.h>
#include <cstdint>
#include <math.h>

// Problem constants
#define B_   4
#define N_   2048
#define D_   1024
#define H_   16
#define HD_  64
#define E3_  192          // 3 * head_dim, chunk order (k, q, v)
#define MROWS (B_ * N_)   // 8192

#define NEG_INF (-1e30f)

// Scratch (allocation-free rule: __device__ globals)
__device__ float g_kqv[(size_t)B_ * H_ * N_ * E3_];   // [b][h][n][e] (tf32-rounded)
__device__ float g_sa [(size_t)B_ * N_ * D_];         // [b][n][h*hd+d] (tf32-rounded)
__device__ float g_xt [(size_t)MROWS * D_];           // x, tf32-rounded
__device__ float g_wt_kqv[(size_t)H_ * E3_ * D_];     // W_kqv^T [h][e][k], tf32-rounded
__device__ float g_wt_proj[(size_t)D_ * D_];          // W_proj^T [n][k], tf32-rounded

// ---------------------------------------------------------------------------
// Helpers
// ---------------------------------------------------------------------------
__device__ __forceinline__ float rtf(float x) {   // round-to-nearest tf32
    uint32_t u;
    asm("cvt.rna.tf32.f32 %0, %1;" : "=r"(u) : "f"(x));
    return __uint_as_float(u);
}
__device__ __forceinline__ void cpa16(uint32_t dst, const void* src) {
    asm volatile("cp.async.ca.shared.global [%0], [%1], 16;" :: "r"(dst), "l"(src));
}
__device__ __forceinline__ void cpa4(uint32_t dst, const void* src) {
    asm volatile("cp.async.ca.shared.global [%0], [%1], 4;" :: "r"(dst), "l"(src));
}
__device__ __forceinline__ uint32_t smem_u32(const void* p) {
    uint32_t a;
    asm("{ .reg .u64 t; cvta.to.shared.u64 t, %1; cvt.u32.u64 %0, t; }"
        : "=r"(a) : "l"(p));
    return a;
}
__device__ __forceinline__ void mma_tf32(float* c, const uint32_t* a, const uint32_t* b) {
    asm volatile(
        "mma.sync.aligned.m16n8k8.row.col.f32.tf32.tf32.f32 "
        "{%0,%1,%2,%3}, {%4,%5,%6,%7}, {%8,%9}, {%0,%1,%2,%3};"
        : "+f"(c[0]), "+f"(c[1]), "+f"(c[2]), "+f"(c[3])
        : "r"(a[0]), "r"(a[1]), "r"(a[2]), "r"(a[3]), "r"(b[0]), "r"(b[1]));
}

// ---------------------------------------------------------------------------
// Prep kernels: tf32-round x; transpose+round weights to [n][k]
// ---------------------------------------------------------------------------
__global__ void rtf_x_kernel(const float* __restrict__ x) {
    size_t i = ((size_t)blockIdx.x * 256 + threadIdx.x) * 4;
    float4 v = *(const float4*)(x + i);
    v.x = rtf(v.x); v.y = rtf(v.y); v.z = rtf(v.z); v.w = rtf(v.w);
    *(float4*)(g_xt + i) = v;
}

__global__ void tr_kqv_kernel(const float* __restrict__ W) {
    __shared__ float t[32][33];
    const int h = blockIdx.z, k0 = blockIdx.x * 32, e0 = blockIdx.y * 32;
    const float* Wh = W + (size_t)h * D_ * E3_;
    float* Wt = g_wt_kqv + (size_t)h * E3_ * D_;
    const int x = threadIdx.x, y = threadIdx.y;
#pragma unroll
    for (int j = 0; j < 32; j += 8)
        t[y + j][x] = Wh[(size_t)(k0 + y + j) * E3_ + e0 + x];
    __syncthreads();
#pragma unroll
    for (int j = 0; j < 32; j += 8)
        Wt[(size_t)(e0 + y + j) * D_ + k0 + x] = rtf(t[x][y + j]);
}

__global__ void tr_proj_kernel(const float* __restrict__ W) {
    __shared__ float t[32][33];
    const int k0 = blockIdx.x * 32, n0 = blockIdx.y * 32;
    const int x = threadIdx.x, y = threadIdx.y;
#pragma unroll
    for (int j = 0; j < 32; j += 8)
        t[y + j][x] = W[(size_t)(k0 + y + j) * D_ + n0 + x];
    __syncthreads();
#pragma unroll
    for (int j = 0; j < 32; j += 8)
        g_wt_proj[(size_t)(n0 + y + j) * D_ + k0 + x] = rtf(t[x][y + j]);
}

// ---------------------------------------------------------------------------
// tf32 mma.sync GEMM. CTA tile 128 x NT, K=1024 in chunks of 32.
// PER_HEAD=1 stores g_kqv tf32-rounded so attention frags need no conversion.
// ---------------------------------------------------------------------------
template <int NT, int PER_HEAD>
__global__ __launch_bounds__(256, 1) void gemm_mma_kernel(
    const float* __restrict__ bias, float* __restrict__ Cout)
{
    constexpr int NSUB = NT / 32;
    constexpr int AST = 128 * 36;
    constexpr int BST = NT * 36;
    extern __shared__ float sm[];
    float* As = sm;
    float* Bs = sm + 2 * AST;

    const int tid  = threadIdx.x;
    const int m0   = blockIdx.x * 128;
    const int head = blockIdx.y;
    const int n0   = PER_HEAD ? 0 : blockIdx.y * NT;

    const float* Ab = (PER_HEAD ? g_xt : g_sa) + (size_t)m0 * D_;
    const float* Bt = PER_HEAD ? (g_wt_kqv + (size_t)head * E3_ * D_)
                               : (g_wt_proj + (size_t)n0 * D_);

    const uint32_t sA = smem_u32(As);
    const uint32_t sB = smem_u32(Bs);

    auto load_stage = [&](int kc, int buf) {
        const float* ap = Ab + kc * 32;
        const uint32_t da = sA + (uint32_t)buf * AST * 4;
#pragma unroll
        for (int j = 0; j < 4; ++j) {
            const int idx = tid + j * 256;
            const int r = idx >> 3, q = (idx & 7) << 2;
            cpa16(da + (uint32_t)(r * 36 + q) * 4, ap + (size_t)r * D_ + q);
        }
        const float* bp = Bt + kc * 32;
        const uint32_t db = sB + (uint32_t)buf * BST * 4;
#pragma unroll
        for (int j = 0; j < NT / 32; ++j) {
            const int idx = tid + j * 256;
            const int r = idx >> 3, q = (idx & 7) << 2;
            cpa16(db + (uint32_t)(r * 36 + q) * 4, bp + (size_t)r * D_ + q);
        }
        asm volatile("cp.async.commit_group;" ::: "memory");
    };

    const int w    = tid >> 5, lane = tid & 31;
    const int wm   = (w & 1) * 64;
    const int wn   = (w >> 1) * NSUB * 8;
    const int grp  = lane >> 2, tig = lane & 3;

    float acc[4][NSUB][4];
#pragma unroll
    for (int mi = 0; mi < 4; ++mi)
#pragma unroll
        for (int ni = 0; ni < NSUB; ++ni)
#pragma unroll
            for (int r = 0; r < 4; ++r) acc[mi][ni][r] = 0.f;

    load_stage(0, 0);
    load_stage(1, 1);

    for (int kc = 0; kc < 32; ++kc) {
        if (kc < 31) asm volatile("cp.async.wait_group 1;" ::: "memory");
        else         asm volatile("cp.async.wait_group 0;" ::: "memory");
        __syncthreads();
        const float* Ap = As + (kc & 1) * AST;
        const float* Bp = Bs + (kc & 1) * BST;
#pragma unroll
        for (int ks = 0; ks < 4; ++ks) {
            const int k = ks * 8;
            uint32_t a[4][4], bf[NSUB][2];
#pragma unroll
            for (int mi = 0; mi < 4; ++mi) {
                const float* p = Ap + (wm + mi * 16 + grp) * 36 + k + tig;
                a[mi][0] = __float_as_uint(p[0]);
                a[mi][1] = __float_as_uint(p[8 * 36]);
                a[mi][2] = __float_as_uint(p[4]);
                a[mi][3] = __float_as_uint(p[8 * 36 + 4]);
            }
#pragma unroll
            for (int ni = 0; ni < NSUB; ++ni) {
                const float* p = Bp + (wn + ni * 8 + grp) * 36 + k + tig;
                bf[ni][0] = __float_as_uint(p[0]);
                bf[ni][1] = __float_as_uint(p[4]);
            }
#pragma unroll
            for (int mi = 0; mi < 4; ++mi)
#pragma unroll
                for (int ni = 0; ni < NSUB; ++ni)
                    mma_tf32(acc[mi][ni], a[mi], bf[ni]);
        }
        __syncthreads();
        if (kc + 2 < 32) load_stage(kc + 2, kc & 1);
    }

#pragma unroll
    for (int mi = 0; mi < 4; ++mi) {
        const int mbase = m0 + wm + mi * 16 + grp;
#pragma unroll
        for (int half = 0; half < 2; ++half) {
            const int m = mbase + half * 8;
            float* dst;
            const float* bsp;
            if (PER_HEAD) {
                const int b = m >> 11, tok = m & 2047;
                dst = g_kqv + (((size_t)b * H_ + head) * N_ + tok) * E3_;
                bsp = bias + head * E3_;
            } else {
                dst = Cout + (size_t)m * D_ + n0;
                bsp = bias + n0;
            }
#pragma unroll
            for (int ni = 0; ni < NSUB; ++ni) {
                const int c = wn + ni * 8 + 2 * tig;
                float2 o;
                if (PER_HEAD) {
                    o.x = rtf(acc[mi][ni][half * 2 + 0] + bsp[c]);
                    o.y = rtf(acc[mi][ni][half * 2 + 1] + bsp[c + 1]);
                } else {
                    o.x = acc[mi][ni][half * 2 + 0] + bsp[c];
                    o.y = acc[mi][ni][half * 2 + 1] + bsp[c + 1];
                }
                *(float2*)(dst + c) = o;
            }
        }
    }
}

// ---------------------------------------------------------------------------
// Tensor-core causal flash attention.
// CTA = 128 queries of one (b,h); 8 warps, each owns a 16-row strip.
// Key tiles of 64, double-buffered cp.async (K as [n][d], V transposed [d][n]).
// QK^T and P*V via mma.sync m16n8k8 tf32; online softmax per warp.
// g_kqv is tf32-rounded at the source, so frags need no conversion.
// ---------------------------------------------------------------------------
#define BM 128
#define BK 64
#define KST (64 * 68)

__global__ __launch_bounds__(256, 1) void attn_mma_kernel()
{
    extern __shared__ float sm[];
    float* Kb = sm;                 // [2][KST]  K tiles [n][d], stride 68
    float* Vt = sm + 2 * KST;       // [2][KST]  V^T tiles [d][n], stride 68
    float* Pb = sm + 4 * KST;       // [128][68] Q stage, then P per-warp strips

    const int qi  = (int)(gridDim.x - 1 - blockIdx.x);  // heavy tiles first
    const int h   = blockIdx.y, b = blockIdx.z;
    const int tid = threadIdx.x;
    const int w   = tid >> 5, lane = tid & 31;
    const int grp = lane >> 2, tig = lane & 3;
    const int m0  = qi * BM;
    const size_t base = ((size_t)b * H_ + h) * N_ * E3_;

    const uint32_t uKb = smem_u32(Kb);
    const uint32_t uVt = smem_u32(Vt);
    const uint32_t uPb = smem_u32(Pb);

    // Stage Q (128 x 64) into Pb
    {
        const float* q0 = g_kqv + base + (size_t)m0 * E3_ + HD_;
#pragma unroll
        for (int j = 0; j < 8; ++j) {
            const int i = tid + j * 256;
            const int r = i >> 4, c = (i & 15) << 2;
            cpa16(uPb + (uint32_t)(r * 68 + c) * 4, q0 + (size_t)r * E3_ + c);
        }
        asm volatile("cp.async.commit_group;" ::: "memory");
    }

    auto load_kv = [&](int kt, int bufi) {
        const float* kp = g_kqv + base + (size_t)(kt * BK) * E3_;
        const uint32_t kd = uKb + (uint32_t)bufi * KST * 4;
#pragma unroll
        for (int j = 0; j < 4; ++j) {
            const int i = tid + j * 256;
            const int n = i >> 4, c = (i & 15) << 2;
            cpa16(kd + (uint32_t)(n * 68 + c) * 4, kp + (size_t)n * E3_ + c);
        }
        const float* vp = kp + 2 * HD_;
        const uint32_t vd = uVt + (uint32_t)bufi * KST * 4;
#pragma unroll
        for (int j = 0; j < 16; ++j) {
            const int i = tid + j * 256;
            const int n = i & 63, d = i >> 6;
            cpa4(vd + (uint32_t)(d * 68 + n) * 4, vp + (size_t)n * E3_ + d);
        }
        asm volatile("cp.async.commit_group;" ::: "memory");
    };

    load_kv(0, 0);

    asm volatile("cp.async.wait_group 1;" ::: "memory");  // Q stage done
    __syncthreads();

    // Q fragments in registers for the whole kernel (0.125 scale is exact)
    uint32_t qf[8][4];
    {
        const float* Pw = Pb + (w * 16) * 68;
#pragma unroll
        for (int ks = 0; ks < 8; ++ks) {
            const int k = ks * 8 + tig;
            qf[ks][0] = __float_as_uint(Pw[grp * 68 + k] * 0.125f);
            qf[ks][1] = __float_as_uint(Pw[(grp + 8) * 68 + k] * 0.125f);
            qf[ks][2] = __float_as_uint(Pw[grp * 68 + k + 4] * 0.125f);
            qf[ks][3] = __float_as_uint(Pw[(grp + 8) * 68 + k + 4] * 0.125f);
        }
    }
    __syncthreads();

    const int r0    = m0 + w * 16 + grp;
    const int r1    = r0 + 8;
    const int rmax  = m0 + w * 16 + 15;
    const int nt    = (m0 + BM) / BK;
    const int diag0 = m0 / BK;

    float oacc[8][4];
#pragma unroll
    for (int ni = 0; ni < 8; ++ni)
#pragma unroll
        for (int r = 0; r < 4; ++r) oacc[ni][r] = 0.f;
    float mr0 = NEG_INF, mr1 = NEG_INF, l0 = 0.f, l1 = 0.f;

    float* prow0 = Pb + (w * 16 + grp) * 68;
    float* prow1 = prow0 + 8 * 68;

    for (int kt = 0; kt < nt; ++kt) {
        asm volatile("cp.async.wait_group 0;" ::: "memory");
        __syncthreads();
        if (kt + 1 < nt) load_kv(kt + 1, (kt + 1) & 1);

        if (kt * BK <= rmax) {
            const float* Kp = Kb + (kt & 1) * KST;
            const float* Vp = Vt + (kt & 1) * KST;

            // S = Q K^T
            float s[8][4];
#pragma unroll
            for (int ni = 0; ni < 8; ++ni)
#pragma unroll
                for (int r = 0; r < 4; ++r) s[ni][r] = 0.f;
#pragma unroll
            for (int ks = 0; ks < 8; ++ks) {
                const int k = ks * 8 + tig;
                uint32_t bf[8][2];
#pragma unroll
                for (int ni = 0; ni < 8; ++ni) {
                    const float* p = Kp + (ni * 8 + grp) * 68 + k;
                    bf[ni][0] = __float_as_uint(p[0]);
                    bf[ni][1] = __float_as_uint(p[4]);
                }
#pragma unroll
                for (int ni = 0; ni < 8; ++ni)
                    mma_tf32(s[ni], qf[ks], bf[ni]);
            }

            // Causal mask (only for diagonal-overlapping tiles)
            if (kt >= diag0) {
                const int colb = kt * BK;
#pragma unroll
                for (int ni = 0; ni < 8; ++ni) {
                    const int c = colb + ni * 8 + 2 * tig;
                    if (c > r0)     s[ni][0] = NEG_INF;
                    if (c + 1 > r0) s[ni][1] = NEG_INF;
                    if (c > r1)     s[ni][2] = NEG_INF;
                    if (c + 1 > r1) s[ni][3] = NEG_INF;
                }
            }

            // Online softmax (rows r0, r1); quad = 4 consecutive lanes
            float mx0 = NEG_INF, mx1 = NEG_INF;
#pragma unroll
            for (int ni = 0; ni < 8; ++ni) {
                mx0 = fmaxf(mx0, fmaxf(s[ni][0], s[ni][1]));
                mx1 = fmaxf(mx1, fmaxf(s[ni][2], s[ni][3]));
            }
            mx0 = fmaxf(mx0, __shfl_xor_sync(0xffffffffu, mx0, 1));
            mx0 = fmaxf(mx0, __shfl_xor_sync(0xffffffffu, mx0, 2));
            mx1 = fmaxf(mx1, __shfl_xor_sync(0xffffffffu, mx1, 1));
            mx1 = fmaxf(mx1, __shfl_xor_sync(0xffffffffu, mx1, 2));

            const float mn0 = fmaxf(mr0, mx0), mn1 = fmaxf(mr1, mx1);
            const float a0 = __expf(mr0 - mn0), a1 = __expf(mr1 - mn1);
            float sum0 = 0.f, sum1 = 0.f;
#pragma unroll
            for (int ni = 0; ni < 8; ++ni) {
                s[ni][0] = __expf(s[ni][0] - mn0);
                s[ni][1] = __expf(s[ni][1] - mn0);
                s[ni][2] = __expf(s[ni][2] - mn1);
                s[ni][3] = __expf(s[ni][3] - mn1);
                sum0 += s[ni][0] + s[ni][1];
                sum1 += s[ni][2] + s[ni][3];
            }
            sum0 += __shfl_xor_sync(0xffffffffu, sum0, 1);
            sum0 += __shfl_xor_sync(0xffffffffu, sum0, 2);
            sum1 += __shfl_xor_sync(0xffffffffu, sum1, 1);
            sum1 += __shfl_xor_sync(0xffffffffu, sum1, 2);

            l0 = l0 * a0 + sum0;  mr0 = mn0;
            l1 = l1 * a1 + sum1;  mr1 = mn1;
#pragma unroll
            for (int ni = 0; ni < 8; ++ni) {
                oacc[ni][0] *= a0; oacc[ni][1] *= a0;
                oacc[ni][2] *= a1; oacc[ni][3] *= a1;
            }

            // Store P (tf32-rounded) into this warp's private strip
#pragma unroll
            for (int ni = 0; ni < 8; ++ni) {
                const int c = ni * 8 + 2 * tig;
                prow0[c]     = rtf(s[ni][0]);
                prow0[c + 1] = rtf(s[ni][1]);
                prow1[c]     = rtf(s[ni][2]);
                prow1[c + 1] = rtf(s[ni][3]);
            }
            __syncwarp();

            // O += P V   (A = P from smem, B = V^T)
#pragma unroll
            for (int ks = 0; ks < 8; ++ks) {
                const int k = ks * 8 + tig;
                uint32_t a[4];
                a[0] = __float_as_uint(prow0[k]);
                a[1] = __float_as_uint(prow1[k]);
                a[2] = __float_as_uint(prow0[k + 4]);
                a[3] = __float_as_uint(prow1[k + 4]);
                uint32_t bf[8][2];
#pragma unroll
                for (int ni = 0; ni < 8; ++ni) {
                    const float* p = Vp + (ni * 8 + grp) * 68 + k;
                    bf[ni][0] = __float_as_uint(p[0]);
                    bf[ni][1] = __float_as_uint(p[4]);
                }
#pragma unroll
                for (int ni = 0; ni < 8; ++ni)
                    mma_tf32(oacc[ni], a, bf[ni]);
            }
        }
    }

    // Epilogue: normalize, tf32-round (proj GEMM consumes g_sa), store
    const float inv0 = 1.0f / l0, inv1 = 1.0f / l1;
    float* d0 = g_sa + ((size_t)b * N_ + r0) * D_ + h * HD_;
    float* d1 = g_sa + ((size_t)b * N_ + r1) * D_ + h * HD_;
#pragma unroll
    for (int ni = 0; ni < 8; ++ni) {
        const int c = ni * 8 + 2 * tig;
        float2 o0, o1;
        o0.x = rtf(oacc[ni][0] * inv0); o0.y = rtf(oacc[ni][1] * inv0);
        o1.x = rtf(oacc[ni][2] * inv1); o1.y = rtf(oacc[ni][3] * inv1);
        *(float2*)(d0 + c) = o0;
        *(float2*)(d1 + c) = o1;
    }
}

// ---------------------------------------------------------------------------
extern "C" void kernel_launch(void* const* d_in, const int* in_sizes, int n_in,
                              void* d_out, int out_size)
{
    const float* x      = (const float*)d_in[0];
    const float* W_kqv  = (const float*)d_in[1];
    const float* b_kqv  = (const float*)d_in[2];
    const float* W_proj = (const float*)d_in[3];
    const float* b_proj = (const float*)d_in[4];
    float* out = (float*)d_out;

    const int SMEM_Q = (2 * 128 * 36 + 2 * E3_ * 36) * 4;   // 92160
    const int SMEM_P = (2 * 128 * 36 + 2 * 128 * 36) * 4;   // 73728
    const int SMEM_A = (4 * KST + 128 * 68) * 4;            // 104448
    cudaFuncSetAttribute(gemm_mma_kernel<E3_, 1>,
                         cudaFuncAttributeMaxDynamicSharedMemorySize, SMEM_Q);
    cudaFuncSetAttribute(gemm_mma_kernel<128, 0>,
                         cudaFuncAttributeMaxDynamicSharedMemorySize, SMEM_P);
    cudaFuncSetAttribute(attn_mma_kernel,
                         cudaFuncAttributeMaxDynamicSharedMemorySize, SMEM_A);

    rtf_x_kernel<<<MROWS * D_ / 1024, 256>>>(x);
    tr_kqv_kernel<<<dim3(D_ / 32, E3_ / 32, H_), dim3(32, 8)>>>(W_kqv);
    tr_proj_kernel<<<dim3(D_ / 32, D_ / 32), dim3(32, 8)>>>(W_proj);

    gemm_mma_kernel<E3_, 1><<<dim3(MROWS / 128, H_), 256, SMEM_Q>>>(b_kqv, nullptr);
    attn_mma_kernel<<<dim3(N_ / BM, H_, B_), 256, SMEM_A>>>();
    gemm_mma_kernel<128, 0><<<dim3(MROWS / 128, D_ / 128), 256, SMEM_P>>>(b_proj, out);
}

// round 7
// speedup vs baseline: 2.9535x; 1.0440x over previous
#include <cuda_runtime.h>
#include <cstdint>
#include <math.h>

// Problem constants
#define B_   4
#define N_   2048
#define D_   1024
#define H_   16
#define HD_  64
#define E3_  192          // 3 * head_dim, chunk order (k, q, v)
#define MROWS (B_ * N_)   // 8192

#define NEG_INF (-1e30f)

// Scratch (allocation-free rule: __device__ globals)
__device__ float g_kqv[(size_t)B_ * H_ * N_ * E3_];   // [b][h][n][e] (tf32-rounded)
__device__ float g_sa [(size_t)B_ * N_ * D_];         // [b][n][h*hd+d] (tf32-rounded)
__device__ float g_xt [(size_t)MROWS * D_];           // x, tf32-rounded
__device__ float g_wt_kqv[(size_t)H_ * E3_ * D_];     // W_kqv^T [h][e][k], tf32-rounded
__device__ float g_wt_proj[(size_t)D_ * D_];          // W_proj^T [n][k], tf32-rounded

// ---------------------------------------------------------------------------
// Helpers
// ---------------------------------------------------------------------------
__device__ __forceinline__ float rtf(float x) {   // round-to-nearest tf32
    uint32_t u;
    asm("cvt.rna.tf32.f32 %0, %1;" : "=r"(u) : "f"(x));
    return __uint_as_float(u);
}
__device__ __forceinline__ void cpa16(uint32_t dst, const void* src) {
    asm volatile("cp.async.ca.shared.global [%0], [%1], 16;" :: "r"(dst), "l"(src));
}
__device__ __forceinline__ void cpa4(uint32_t dst, const void* src) {
    asm volatile("cp.async.ca.shared.global [%0], [%1], 4;" :: "r"(dst), "l"(src));
}
__device__ __forceinline__ uint32_t smem_u32(const void* p) {
    uint32_t a;
    asm("{ .reg .u64 t; cvta.to.shared.u64 t, %1; cvt.u32.u64 %0, t; }"
        : "=r"(a) : "l"(p));
    return a;
}
__device__ __forceinline__ void mma_tf32(float* c, const uint32_t* a, const uint32_t* b) {
    asm volatile(
        "mma.sync.aligned.m16n8k8.row.col.f32.tf32.tf32.f32 "
        "{%0,%1,%2,%3}, {%4,%5,%6,%7}, {%8,%9}, {%0,%1,%2,%3};"
        : "+f"(c[0]), "+f"(c[1]), "+f"(c[2]), "+f"(c[3])
        : "r"(a[0]), "r"(a[1]), "r"(a[2]), "r"(a[3]), "r"(b[0]), "r"(b[1]));
}
// ldmatrix x4 over f32 data (b16-pair trick): reg m of lane i = f32 element
// (i%4) of row (i/4) of matrix m. Lane j supplies address of row (j%8) of
// matrix (j/8); each row is 16B = 4 f32.
__device__ __forceinline__ void ldsm4(uint32_t* r, uint32_t addr) {
    asm volatile(
        "ldmatrix.sync.aligned.m8n8.x4.shared.b16 {%0,%1,%2,%3}, [%4];"
        : "=r"(r[0]), "=r"(r[1]), "=r"(r[2]), "=r"(r[3]) : "r"(addr));
}

// ---------------------------------------------------------------------------
// Prep kernels: tf32-round x; transpose+round weights to [n][k]
// ---------------------------------------------------------------------------
__global__ void rtf_x_kernel(const float* __restrict__ x) {
    size_t i = ((size_t)blockIdx.x * 256 + threadIdx.x) * 4;
    float4 v = *(const float4*)(x + i);
    v.x = rtf(v.x); v.y = rtf(v.y); v.z = rtf(v.z); v.w = rtf(v.w);
    *(float4*)(g_xt + i) = v;
}

__global__ void tr_kqv_kernel(const float* __restrict__ W) {
    __shared__ float t[32][33];
    const int h = blockIdx.z, k0 = blockIdx.x * 32, e0 = blockIdx.y * 32;
    const float* Wh = W + (size_t)h * D_ * E3_;
    float* Wt = g_wt_kqv + (size_t)h * E3_ * D_;
    const int x = threadIdx.x, y = threadIdx.y;
#pragma unroll
    for (int j = 0; j < 32; j += 8)
        t[y + j][x] = Wh[(size_t)(k0 + y + j) * E3_ + e0 + x];
    __syncthreads();
#pragma unroll
    for (int j = 0; j < 32; j += 8)
        Wt[(size_t)(e0 + y + j) * D_ + k0 + x] = rtf(t[x][y + j]);
}

__global__ void tr_proj_kernel(const float* __restrict__ W) {
    __shared__ float t[32][33];
    const int k0 = blockIdx.x * 32, n0 = blockIdx.y * 32;
    const int x = threadIdx.x, y = threadIdx.y;
#pragma unroll
    for (int j = 0; j < 32; j += 8)
        t[y + j][x] = W[(size_t)(k0 + y + j) * D_ + n0 + x];
    __syncthreads();
#pragma unroll
    for (int j = 0; j < 32; j += 8)
        g_wt_proj[(size_t)(n0 + y + j) * D_ + k0 + x] = rtf(t[x][y + j]);
}

// ---------------------------------------------------------------------------
// tf32 mma.sync GEMM. CTA tile 128 x NT, K=1024 in chunks of 32.
// Fragment loads via ldmatrix.x4 (1 instr per 16x8 A-frag / per 2 B-frags).
// ---------------------------------------------------------------------------
template <int NT, int PER_HEAD>
__global__ __launch_bounds__(256, 1) void gemm_mma_kernel(
    const float* __restrict__ bias, float* __restrict__ Cout)
{
    constexpr int NSUB = NT / 32;
    constexpr int AST = 128 * 36;
    constexpr int BST = NT * 36;
    extern __shared__ float sm[];
    float* As = sm;
    float* Bs = sm + 2 * AST;

    const int tid  = threadIdx.x;
    const int m0   = blockIdx.x * 128;
    const int head = blockIdx.y;
    const int n0   = PER_HEAD ? 0 : blockIdx.y * NT;

    const float* Ab = (PER_HEAD ? g_xt : g_sa) + (size_t)m0 * D_;
    const float* Bt = PER_HEAD ? (g_wt_kqv + (size_t)head * E3_ * D_)
                               : (g_wt_proj + (size_t)n0 * D_);

    const uint32_t sA = smem_u32(As);
    const uint32_t sB = smem_u32(Bs);

    auto load_stage = [&](int kc, int buf) {
        const float* ap = Ab + kc * 32;
        const uint32_t da = sA + (uint32_t)buf * AST * 4;
#pragma unroll
        for (int j = 0; j < 4; ++j) {
            const int idx = tid + j * 256;
            const int r = idx >> 3, q = (idx & 7) << 2;
            cpa16(da + (uint32_t)(r * 36 + q) * 4, ap + (size_t)r * D_ + q);
        }
        const float* bp = Bt + kc * 32;
        const uint32_t db = sB + (uint32_t)buf * BST * 4;
#pragma unroll
        for (int j = 0; j < NT / 32; ++j) {
            const int idx = tid + j * 256;
            const int r = idx >> 3, q = (idx & 7) << 2;
            cpa16(db + (uint32_t)(r * 36 + q) * 4, bp + (size_t)r * D_ + q);
        }
        asm volatile("cp.async.commit_group;" ::: "memory");
    };

    const int w    = tid >> 5, lane = tid & 31;
    const int wm   = (w & 1) * 64;
    const int wn   = (w >> 1) * NSUB * 8;
    const int grp  = lane >> 2, tig = lane & 3;

    // ldmatrix lane->address row/col offsets
    const int lrA = ((lane >> 3) & 1) * 8 + (lane & 7);  // A: mat&1 -> +8 rows
    const int lcA = ((lane >> 4) & 1) * 4;               //    mat>>1 -> +4 cols
    const int lrB = ((lane >> 4) & 1) * 8 + (lane & 7);  // B: mat>>1 -> +8 rows
    const int lcB = ((lane >> 3) & 1) * 4;               //    mat&1 -> +4 cols

    float acc[4][NSUB][4];
#pragma unroll
    for (int mi = 0; mi < 4; ++mi)
#pragma unroll
        for (int ni = 0; ni < NSUB; ++ni)
#pragma unroll
            for (int r = 0; r < 4; ++r) acc[mi][ni][r] = 0.f;

    load_stage(0, 0);
    load_stage(1, 1);

    for (int kc = 0; kc < 32; ++kc) {
        if (kc < 31) asm volatile("cp.async.wait_group 1;" ::: "memory");
        else         asm volatile("cp.async.wait_group 0;" ::: "memory");
        __syncthreads();
        const uint32_t uAp = sA + (uint32_t)(kc & 1) * AST * 4;
        const uint32_t uBp = sB + (uint32_t)(kc & 1) * BST * 4;
#pragma unroll
        for (int ks = 0; ks < 4; ++ks) {
            const int k = ks * 8;
            uint32_t a[4][4], bf[NSUB][2];
#pragma unroll
            for (int mi = 0; mi < 4; ++mi)
                ldsm4(a[mi], uAp + (uint32_t)((wm + mi * 16 + lrA) * 36 + k + lcA) * 4);
#pragma unroll
            for (int np = 0; np < NSUB / 2; ++np) {
                uint32_t r[4];
                ldsm4(r, uBp + (uint32_t)((wn + np * 16 + lrB) * 36 + k + lcB) * 4);
                bf[2 * np][0] = r[0]; bf[2 * np][1] = r[1];
                bf[2 * np + 1][0] = r[2]; bf[2 * np + 1][1] = r[3];
            }
#pragma unroll
            for (int mi = 0; mi < 4; ++mi)
#pragma unroll
                for (int ni = 0; ni < NSUB; ++ni)
                    mma_tf32(acc[mi][ni], a[mi], bf[ni]);
        }
        __syncthreads();
        if (kc + 2 < 32) load_stage(kc + 2, kc & 1);
    }

#pragma unroll
    for (int mi = 0; mi < 4; ++mi) {
        const int mbase = m0 + wm + mi * 16 + grp;
#pragma unroll
        for (int half = 0; half < 2; ++half) {
            const int m = mbase + half * 8;
            float* dst;
            const float* bsp;
            if (PER_HEAD) {
                const int b = m >> 11, tok = m & 2047;
                dst = g_kqv + (((size_t)b * H_ + head) * N_ + tok) * E3_;
                bsp = bias + head * E3_;
            } else {
                dst = Cout + (size_t)m * D_ + n0;
                bsp = bias + n0;
            }
#pragma unroll
            for (int ni = 0; ni < NSUB; ++ni) {
                const int c = wn + ni * 8 + 2 * tig;
                float2 o;
                if (PER_HEAD) {
                    o.x = rtf(acc[mi][ni][half * 2 + 0] + bsp[c]);
                    o.y = rtf(acc[mi][ni][half * 2 + 1] + bsp[c + 1]);
                } else {
                    o.x = acc[mi][ni][half * 2 + 0] + bsp[c];
                    o.y = acc[mi][ni][half * 2 + 1] + bsp[c + 1];
                }
                *(float2*)(dst + c) = o;
            }
        }
    }
}

// ---------------------------------------------------------------------------
// Tensor-core causal flash attention, frag loads via ldmatrix.
// CTA = 128 queries of one (b,h); 8 warps, each owns a 16-row strip.
// ---------------------------------------------------------------------------
#define BM 128
#define BK 64
#define KST (64 * 68)

__global__ __launch_bounds__(256, 1) void attn_mma_kernel()
{
    extern __shared__ float sm[];
    float* Kb = sm;                 // [2][KST]  K tiles [n][d], stride 68
    float* Vt = sm + 2 * KST;       // [2][KST]  V^T tiles [d][n], stride 68
    float* Pb = sm + 4 * KST;       // [128][68] Q stage, then P per-warp strips

    const int qi  = (int)(gridDim.x - 1 - blockIdx.x);  // heavy tiles first
    const int h   = blockIdx.y, b = blockIdx.z;
    const int tid = threadIdx.x;
    const int w   = tid >> 5, lane = tid & 31;
    const int grp = lane >> 2, tig = lane & 3;
    const int m0  = qi * BM;
    const size_t base = ((size_t)b * H_ + h) * N_ * E3_;

    const uint32_t uKb = smem_u32(Kb);
    const uint32_t uVt = smem_u32(Vt);
    const uint32_t uPb = smem_u32(Pb);

    const int lrA = ((lane >> 3) & 1) * 8 + (lane & 7);
    const int lcA = ((lane >> 4) & 1) * 4;
    const int lrB = ((lane >> 4) & 1) * 8 + (lane & 7);
    const int lcB = ((lane >> 3) & 1) * 4;

    // Stage Q (128 x 64) into Pb
    {
        const float* q0 = g_kqv + base + (size_t)m0 * E3_ + HD_;
#pragma unroll
        for (int j = 0; j < 8; ++j) {
            const int i = tid + j * 256;
            const int r = i >> 4, c = (i & 15) << 2;
            cpa16(uPb + (uint32_t)(r * 68 + c) * 4, q0 + (size_t)r * E3_ + c);
        }
        asm volatile("cp.async.commit_group;" ::: "memory");
    }

    auto load_kv = [&](int kt, int bufi) {
        const float* kp = g_kqv + base + (size_t)(kt * BK) * E3_;
        const uint32_t kd = uKb + (uint32_t)bufi * KST * 4;
#pragma unroll
        for (int j = 0; j < 4; ++j) {
            const int i = tid + j * 256;
            const int n = i >> 4, c = (i & 15) << 2;
            cpa16(kd + (uint32_t)(n * 68 + c) * 4, kp + (size_t)n * E3_ + c);
        }
        const float* vp = kp + 2 * HD_;
        const uint32_t vd = uVt + (uint32_t)bufi * KST * 4;
#pragma unroll
        for (int j = 0; j < 16; ++j) {
            const int i = tid + j * 256;
            const int n = i & 63, d = i >> 6;
            cpa4(vd + (uint32_t)(d * 68 + n) * 4, vp + (size_t)n * E3_ + d);
        }
        asm volatile("cp.async.commit_group;" ::: "memory");
    };

    load_kv(0, 0);

    asm volatile("cp.async.wait_group 1;" ::: "memory");  // Q stage done
    __syncthreads();

    // Q fragments in registers for the whole kernel (0.125 scale is exact)
    uint32_t qf[8][4];
    {
        const float* Pw = Pb + (w * 16) * 68;
#pragma unroll
        for (int ks = 0; ks < 8; ++ks) {
            const int k = ks * 8 + tig;
            qf[ks][0] = __float_as_uint(Pw[grp * 68 + k] * 0.125f);
            qf[ks][1] = __float_as_uint(Pw[(grp + 8) * 68 + k] * 0.125f);
            qf[ks][2] = __float_as_uint(Pw[grp * 68 + k + 4] * 0.125f);
            qf[ks][3] = __float_as_uint(Pw[(grp + 8) * 68 + k + 4] * 0.125f);
        }
    }
    __syncthreads();

    const int r0    = m0 + w * 16 + grp;
    const int r1    = r0 + 8;
    const int rmax  = m0 + w * 16 + 15;
    const int nt    = (m0 + BM) / BK;
    const int diag0 = m0 / BK;

    float oacc[8][4];
#pragma unroll
    for (int ni = 0; ni < 8; ++ni)
#pragma unroll
        for (int r = 0; r < 4; ++r) oacc[ni][r] = 0.f;
    float mr0 = NEG_INF, mr1 = NEG_INF, l0 = 0.f, l1 = 0.f;

    float* prow0 = Pb + (w * 16 + grp) * 68;
    float* prow1 = prow0 + 8 * 68;
    const uint32_t uPw = uPb + (uint32_t)(w * 16 + lrA) * 68 * 4;

    for (int kt = 0; kt < nt; ++kt) {
        asm volatile("cp.async.wait_group 0;" ::: "memory");
        __syncthreads();
        if (kt + 1 < nt) load_kv(kt + 1, (kt + 1) & 1);

        if (kt * BK <= rmax) {
            const uint32_t uKp = uKb + (uint32_t)(kt & 1) * KST * 4;
            const uint32_t uVp = uVt + (uint32_t)(kt & 1) * KST * 4;

            // S = Q K^T
            float s[8][4];
#pragma unroll
            for (int ni = 0; ni < 8; ++ni)
#pragma unroll
                for (int r = 0; r < 4; ++r) s[ni][r] = 0.f;
#pragma unroll
            for (int ks = 0; ks < 8; ++ks) {
                const int k = ks * 8;
                uint32_t bf[8][2];
#pragma unroll
                for (int np = 0; np < 4; ++np) {
                    uint32_t r[4];
                    ldsm4(r, uKp + (uint32_t)((np * 16 + lrB) * 68 + k + lcB) * 4);
                    bf[2 * np][0] = r[0]; bf[2 * np][1] = r[1];
                    bf[2 * np + 1][0] = r[2]; bf[2 * np + 1][1] = r[3];
                }
#pragma unroll
                for (int ni = 0; ni < 8; ++ni)
                    mma_tf32(s[ni], qf[ks], bf[ni]);
            }

            // Causal mask (only for diagonal-overlapping tiles)
            if (kt >= diag0) {
                const int colb = kt * BK;
#pragma unroll
                for (int ni = 0; ni < 8; ++ni) {
                    const int c = colb + ni * 8 + 2 * tig;
                    if (c > r0)     s[ni][0] = NEG_INF;
                    if (c + 1 > r0) s[ni][1] = NEG_INF;
                    if (c > r1)     s[ni][2] = NEG_INF;
                    if (c + 1 > r1) s[ni][3] = NEG_INF;
                }
            }

            // Online softmax (rows r0, r1); quad = 4 consecutive lanes
            float mx0 = NEG_INF, mx1 = NEG_INF;
#pragma unroll
            for (int ni = 0; ni < 8; ++ni) {
                mx0 = fmaxf(mx0, fmaxf(s[ni][0], s[ni][1]));
                mx1 = fmaxf(mx1, fmaxf(s[ni][2], s[ni][3]));
            }
            mx0 = fmaxf(mx0, __shfl_xor_sync(0xffffffffu, mx0, 1));
            mx0 = fmaxf(mx0, __shfl_xor_sync(0xffffffffu, mx0, 2));
            mx1 = fmaxf(mx1, __shfl_xor_sync(0xffffffffu, mx1, 1));
            mx1 = fmaxf(mx1, __shfl_xor_sync(0xffffffffu, mx1, 2));

            const float mn0 = fmaxf(mr0, mx0), mn1 = fmaxf(mr1, mx1);
            const float a0 = __expf(mr0 - mn0), a1 = __expf(mr1 - mn1);
            float sum0 = 0.f, sum1 = 0.f;
#pragma unroll
            for (int ni = 0; ni < 8; ++ni) {
                s[ni][0] = __expf(s[ni][0] - mn0);
                s[ni][1] = __expf(s[ni][1] - mn0);
                s[ni][2] = __expf(s[ni][2] - mn1);
                s[ni][3] = __expf(s[ni][3] - mn1);
                sum0 += s[ni][0] + s[ni][1];
                sum1 += s[ni][2] + s[ni][3];
            }
            sum0 += __shfl_xor_sync(0xffffffffu, sum0, 1);
            sum0 += __shfl_xor_sync(0xffffffffu, sum0, 2);
            sum1 += __shfl_xor_sync(0xffffffffu, sum1, 1);
            sum1 += __shfl_xor_sync(0xffffffffu, sum1, 2);

            l0 = l0 * a0 + sum0;  mr0 = mn0;
            l1 = l1 * a1 + sum1;  mr1 = mn1;
#pragma unroll
            for (int ni = 0; ni < 8; ++ni) {
                oacc[ni][0] *= a0; oacc[ni][1] *= a0;
                oacc[ni][2] *= a1; oacc[ni][3] *= a1;
            }

            // Store P (tf32-rounded) into this warp's private strip
#pragma unroll
            for (int ni = 0; ni < 8; ++ni) {
                const int c = ni * 8 + 2 * tig;
                prow0[c]     = rtf(s[ni][0]);
                prow0[c + 1] = rtf(s[ni][1]);
                prow1[c]     = rtf(s[ni][2]);
                prow1[c + 1] = rtf(s[ni][3]);
            }
            __syncwarp();

            // O += P V   (A = P via ldmatrix, B = V^T via ldmatrix)
#pragma unroll
            for (int ks = 0; ks < 8; ++ks) {
                const int k = ks * 8;
                uint32_t a[4];
                ldsm4(a, uPw + (uint32_t)(k + lcA) * 4);
                uint32_t bf[8][2];
#pragma unroll
                for (int np = 0; np < 4; ++np) {
                    uint32_t r[4];
                    ldsm4(r, uVp + (uint32_t)((np * 16 + lrB) * 68 + k + lcB) * 4);
                    bf[2 * np][0] = r[0]; bf[2 * np][1] = r[1];
                    bf[2 * np + 1][0] = r[2]; bf[2 * np + 1][1] = r[3];
                }
#pragma unroll
                for (int ni = 0; ni < 8; ++ni)
                    mma_tf32(oacc[ni], a, bf[ni]);
            }
            __syncwarp();
        }
    }

    // Epilogue: normalize, tf32-round (proj GEMM consumes g_sa), store
    const float inv0 = 1.0f / l0, inv1 = 1.0f / l1;
    float* d0 = g_sa + ((size_t)b * N_ + r0) * D_ + h * HD_;
    float* d1 = g_sa + ((size_t)b * N_ + r1) * D_ + h * HD_;
#pragma unroll
    for (int ni = 0; ni < 8; ++ni) {
        const int c = ni * 8 + 2 * tig;
        float2 o0, o1;
        o0.x = rtf(oacc[ni][0] * inv0); o0.y = rtf(oacc[ni][1] * inv0);
        o1.x = rtf(oacc[ni][2] * inv1); o1.y = rtf(oacc[ni][3] * inv1);
        *(float2*)(d0 + c) = o0;
        *(float2*)(d1 + c) = o1;
    }
}

// ---------------------------------------------------------------------------
extern "C" void kernel_launch(void* const* d_in, const int* in_sizes, int n_in,
                              void* d_out, int out_size)
{
    const float* x      = (const float*)d_in[0];
    const float* W_kqv  = (const float*)d_in[1];
    const float* b_kqv  = (const float*)d_in[2];
    const float* W_proj = (const float*)d_in[3];
    const float* b_proj = (const float*)d_in[4];
    float* out = (float*)d_out;

    const int SMEM_Q = (2 * 128 * 36 + 2 * E3_ * 36) * 4;   // 92160
    const int SMEM_P = (2 * 128 * 36 + 2 * 128 * 36) * 4;   // 73728
    const int SMEM_A = (4 * KST + 128 * 68) * 4;            // 104448
    cudaFuncSetAttribute(gemm_mma_kernel<E3_, 1>,
                         cudaFuncAttributeMaxDynamicSharedMemorySize, SMEM_Q);
    cudaFuncSetAttribute(gemm_mma_kernel<128, 0>,
                         cudaFuncAttributeMaxDynamicSharedMemorySize, SMEM_P);
    cudaFuncSetAttribute(attn_mma_kernel,
                         cudaFuncAttributeMaxDynamicSharedMemorySize, SMEM_A);

    rtf_x_kernel<<<MROWS * D_ / 1024, 256>>>(x);
    tr_kqv_kernel<<<dim3(D_ / 32, E3_ / 32, H_), dim3(32, 8)>>>(W_kqv);
    tr_proj_kernel<<<dim3(D_ / 32, D_ / 32), dim3(32, 8)>>>(W_proj);

    gemm_mma_kernel<E3_, 1><<<dim3(MROWS / 128, H_), 256, SMEM_Q>>>(b_kqv, nullptr);
    attn_mma_kernel<<<dim3(N_ / BM, H_, B_), 256, SMEM_A>>>();
    gemm_mma_kernel<128, 0><<<dim3(MROWS / 128, D_ / 128), 256, SMEM_P>>>(b_proj, out);
}

// round 8
// speedup vs baseline: 3.0010x; 1.0161x over previous
#include <cuda_runtime.h>
#include <cstdint>
#include <math.h>

// Problem constants
#define B_   4
#define N_   2048
#define D_   1024
#define H_   16
#define HD_  64
#define E3_  192          // 3 * head_dim, chunk order (k, q, v)
#define MROWS (B_ * N_)   // 8192

#define NEG_INF (-1e30f)

// Scratch (allocation-free rule: __device__ globals)
__device__ float g_kqv[(size_t)B_ * H_ * N_ * E3_];   // [b][h][n][e] (tf32-rounded)
__device__ float g_sa [(size_t)B_ * N_ * D_];         // [b][n][h*hd+d] (tf32-rounded)
__device__ float g_xt [(size_t)MROWS * D_];           // x, tf32-rounded
__device__ float g_wt_kqv[(size_t)H_ * E3_ * D_];     // W_kqv^T [h][e][k], tf32-rounded
__device__ float g_wt_proj[(size_t)D_ * D_];          // W_proj^T [n][k], tf32-rounded

// ---------------------------------------------------------------------------
// Helpers
// ---------------------------------------------------------------------------
__device__ __forceinline__ float rtf(float x) {   // round-to-nearest tf32
    uint32_t u;
    asm("cvt.rna.tf32.f32 %0, %1;" : "=r"(u) : "f"(x));
    return __uint_as_float(u);
}
__device__ __forceinline__ float ex2(float x) {   // raw exp2
    float y;
    asm("ex2.approx.f32 %0, %1;" : "=f"(y) : "f"(x));
    return y;
}
__device__ __forceinline__ void cpa16(uint32_t dst, const void* src) {
    asm volatile("cp.async.ca.shared.global [%0], [%1], 16;" :: "r"(dst), "l"(src));
}
__device__ __forceinline__ void cpa4(uint32_t dst, const void* src) {
    asm volatile("cp.async.ca.shared.global [%0], [%1], 4;" :: "r"(dst), "l"(src));
}
__device__ __forceinline__ uint32_t smem_u32(const void* p) {
    uint32_t a;
    asm("{ .reg .u64 t; cvta.to.shared.u64 t, %1; cvt.u32.u64 %0, t; }"
        : "=r"(a) : "l"(p));
    return a;
}
__device__ __forceinline__ void mma_tf32(float* c, const uint32_t* a, const uint32_t* b) {
    asm volatile(
        "mma.sync.aligned.m16n8k8.row.col.f32.tf32.tf32.f32 "
        "{%0,%1,%2,%3}, {%4,%5,%6,%7}, {%8,%9}, {%0,%1,%2,%3};"
        : "+f"(c[0]), "+f"(c[1]), "+f"(c[2]), "+f"(c[3])
        : "r"(a[0]), "r"(a[1]), "r"(a[2]), "r"(a[3]), "r"(b[0]), "r"(b[1]));
}
// ldmatrix x4 over f32 data (b16-pair trick)
__device__ __forceinline__ void ldsm4(uint32_t* r, uint32_t addr) {
    asm volatile(
        "ldmatrix.sync.aligned.m8n8.x4.shared.b16 {%0,%1,%2,%3}, [%4];"
        : "=r"(r[0]), "=r"(r[1]), "=r"(r[2]), "=r"(r[3]) : "r"(addr));
}

// ---------------------------------------------------------------------------
// Prep kernels: tf32-round x; transpose+round weights to [n][k]
// ---------------------------------------------------------------------------
__global__ void rtf_x_kernel(const float* __restrict__ x) {
    size_t i = ((size_t)blockIdx.x * 256 + threadIdx.x) * 4;
    float4 v = *(const float4*)(x + i);
    v.x = rtf(v.x); v.y = rtf(v.y); v.z = rtf(v.z); v.w = rtf(v.w);
    *(float4*)(g_xt + i) = v;
}

__global__ void tr_kqv_kernel(const float* __restrict__ W) {
    __shared__ float t[32][33];
    const int h = blockIdx.z, k0 = blockIdx.x * 32, e0 = blockIdx.y * 32;
    const float* Wh = W + (size_t)h * D_ * E3_;
    float* Wt = g_wt_kqv + (size_t)h * E3_ * D_;
    const int x = threadIdx.x, y = threadIdx.y;
#pragma unroll
    for (int j = 0; j < 32; j += 8)
        t[y + j][x] = Wh[(size_t)(k0 + y + j) * E3_ + e0 + x];
    __syncthreads();
#pragma unroll
    for (int j = 0; j < 32; j += 8)
        Wt[(size_t)(e0 + y + j) * D_ + k0 + x] = rtf(t[x][y + j]);
}

__global__ void tr_proj_kernel(const float* __restrict__ W) {
    __shared__ float t[32][33];
    const int k0 = blockIdx.x * 32, n0 = blockIdx.y * 32;
    const int x = threadIdx.x, y = threadIdx.y;
#pragma unroll
    for (int j = 0; j < 32; j += 8)
        t[y + j][x] = W[(size_t)(k0 + y + j) * D_ + n0 + x];
    __syncthreads();
#pragma unroll
    for (int j = 0; j < 32; j += 8)
        g_wt_proj[(size_t)(n0 + y + j) * D_ + k0 + x] = rtf(t[x][y + j]);
}

// ---------------------------------------------------------------------------
// tf32 mma.sync GEMM. CTA tile 128 x NT, K=1024 in chunks of 32.
// 3-stage cp.async ring, ONE __syncthreads per chunk.
// ---------------------------------------------------------------------------
template <int NT, int PER_HEAD>
__global__ __launch_bounds__(256, 1) void gemm_mma_kernel(
    const float* __restrict__ bias, float* __restrict__ Cout)
{
    constexpr int NSUB = NT / 32;
    constexpr int AST = 128 * 36;
    constexpr int BST = NT * 36;
    extern __shared__ float sm[];
    float* As = sm;                 // [3][AST]
    float* Bs = sm + 3 * AST;       // [3][BST]

    const int tid  = threadIdx.x;
    const int m0   = blockIdx.x * 128;
    const int head = blockIdx.y;
    const int n0   = PER_HEAD ? 0 : blockIdx.y * NT;

    const float* Ab = (PER_HEAD ? g_xt : g_sa) + (size_t)m0 * D_;
    const float* Bt = PER_HEAD ? (g_wt_kqv + (size_t)head * E3_ * D_)
                               : (g_wt_proj + (size_t)n0 * D_);

    const uint32_t sA = smem_u32(As);
    const uint32_t sB = smem_u32(Bs);

    auto load_stage = [&](int kc, int buf) {
        const float* ap = Ab + kc * 32;
        const uint32_t da = sA + (uint32_t)buf * AST * 4;
#pragma unroll
        for (int j = 0; j < 4; ++j) {
            const int idx = tid + j * 256;
            const int r = idx >> 3, q = (idx & 7) << 2;
            cpa16(da + (uint32_t)(r * 36 + q) * 4, ap + (size_t)r * D_ + q);
        }
        const float* bp = Bt + kc * 32;
        const uint32_t db = sB + (uint32_t)buf * BST * 4;
#pragma unroll
        for (int j = 0; j < NT / 32; ++j) {
            const int idx = tid + j * 256;
            const int r = idx >> 3, q = (idx & 7) << 2;
            cpa16(db + (uint32_t)(r * 36 + q) * 4, bp + (size_t)r * D_ + q);
        }
    };

    const int w    = tid >> 5, lane = tid & 31;
    const int wm   = (w & 1) * 64;
    const int wn   = (w >> 1) * NSUB * 8;
    const int grp  = lane >> 2, tig = lane & 3;

    const int lrA = ((lane >> 3) & 1) * 8 + (lane & 7);
    const int lcA = ((lane >> 4) & 1) * 4;
    const int lrB = ((lane >> 4) & 1) * 8 + (lane & 7);
    const int lcB = ((lane >> 3) & 1) * 4;

    float acc[4][NSUB][4];
#pragma unroll
    for (int mi = 0; mi < 4; ++mi)
#pragma unroll
        for (int ni = 0; ni < NSUB; ++ni)
#pragma unroll
            for (int r = 0; r < 4; ++r) acc[mi][ni][r] = 0.f;

    load_stage(0, 0);
    asm volatile("cp.async.commit_group;" ::: "memory");
    load_stage(1, 1);
    asm volatile("cp.async.commit_group;" ::: "memory");

    for (int kc = 0; kc < 32; ++kc) {
        asm volatile("cp.async.wait_group 1;" ::: "memory");
        __syncthreads();
        if (kc + 2 < 32) load_stage(kc + 2, (kc + 2) % 3);
        asm volatile("cp.async.commit_group;" ::: "memory");

        const int st = kc % 3;
        const uint32_t uAp = sA + (uint32_t)st * AST * 4;
        const uint32_t uBp = sB + (uint32_t)st * BST * 4;
#pragma unroll
        for (int ks = 0; ks < 4; ++ks) {
            const int k = ks * 8;
            uint32_t a[4][4], bf[NSUB][2];
#pragma unroll
            for (int mi = 0; mi < 4; ++mi)
                ldsm4(a[mi], uAp + (uint32_t)((wm + mi * 16 + lrA) * 36 + k + lcA) * 4);
#pragma unroll
            for (int np = 0; np < NSUB / 2; ++np) {
                uint32_t r[4];
                ldsm4(r, uBp + (uint32_t)((wn + np * 16 + lrB) * 36 + k + lcB) * 4);
                bf[2 * np][0] = r[0]; bf[2 * np][1] = r[1];
                bf[2 * np + 1][0] = r[2]; bf[2 * np + 1][1] = r[3];
            }
#pragma unroll
            for (int mi = 0; mi < 4; ++mi)
#pragma unroll
                for (int ni = 0; ni < NSUB; ++ni)
                    mma_tf32(acc[mi][ni], a[mi], bf[ni]);
        }
    }

#pragma unroll
    for (int mi = 0; mi < 4; ++mi) {
        const int mbase = m0 + wm + mi * 16 + grp;
#pragma unroll
        for (int half = 0; half < 2; ++half) {
            const int m = mbase + half * 8;
            float* dst;
            const float* bsp;
            if (PER_HEAD) {
                const int b = m >> 11, tok = m & 2047;
                dst = g_kqv + (((size_t)b * H_ + head) * N_ + tok) * E3_;
                bsp = bias + head * E3_;
            } else {
                dst = Cout + (size_t)m * D_ + n0;
                bsp = bias + n0;
            }
#pragma unroll
            for (int ni = 0; ni < NSUB; ++ni) {
                const int c = wn + ni * 8 + 2 * tig;
                float2 o;
                if (PER_HEAD) {
                    o.x = rtf(acc[mi][ni][half * 2 + 0] + bsp[c]);
                    o.y = rtf(acc[mi][ni][half * 2 + 1] + bsp[c + 1]);
                } else {
                    o.x = acc[mi][ni][half * 2 + 0] + bsp[c];
                    o.y = acc[mi][ni][half * 2 + 1] + bsp[c + 1];
                }
                *(float2*)(dst + c) = o;
            }
        }
    }
}

// ---------------------------------------------------------------------------
// Tensor-core causal flash attention with DEFERRED PV pipeline.
// Per iter: QK(kt) mma, PV(kt-1) mma (back-to-back tensor work), then
// softmax(kt) whose latency overlaps the mma pipeline + next-iter sync.
// P double-buffered per-warp strips; V 3-deep ring; K 2-deep.
// Log2-domain softmax: Q pre-scaled by 0.125*log2e, ex2.approx.
// ---------------------------------------------------------------------------
#define BM 128
#define BK 64
#define KST (64 * 68)    // K or V tile (floats)
#define PST (128 * 68)   // P / Q staging buffer (floats)
#define QSCALE (0.125f * 1.44269504088896f)

__global__ __launch_bounds__(256, 1) void attn_mma_kernel()
{
    extern __shared__ float sm[];
    float* Kb = sm;                 // [2][KST]  K tiles [n][d], stride 68
    float* Vt = sm + 2 * KST;       // [3][KST]  V^T tiles [d][n], stride 68
    float* Pq = sm + 5 * KST;       // [2][PST]  P strips (buf0 doubles as Q stage)

    const int qi  = (int)(gridDim.x - 1 - blockIdx.x);  // heavy tiles first
    const int h   = blockIdx.y, b = blockIdx.z;
    const int tid = threadIdx.x;
    const int w   = tid >> 5, lane = tid & 31;
    const int grp = lane >> 2, tig = lane & 3;
    const int m0  = qi * BM;
    const size_t base = ((size_t)b * H_ + h) * N_ * E3_;

    const uint32_t uKb = smem_u32(Kb);
    const uint32_t uVt = smem_u32(Vt);
    const uint32_t uPq = smem_u32(Pq);

    const int lrA = ((lane >> 3) & 1) * 8 + (lane & 7);
    const int lcA = ((lane >> 4) & 1) * 4;
    const int lrB = ((lane >> 4) & 1) * 8 + (lane & 7);
    const int lcB = ((lane >> 3) & 1) * 4;

    // Stage Q (128 x 64) into Pq buffer 0
    {
        const float* q0 = g_kqv + base + (size_t)m0 * E3_ + HD_;
#pragma unroll
        for (int j = 0; j < 8; ++j) {
            const int i = tid + j * 256;
            const int r = i >> 4, c = (i & 15) << 2;
            cpa16(uPq + (uint32_t)(r * 68 + c) * 4, q0 + (size_t)r * E3_ + c);
        }
        asm volatile("cp.async.commit_group;" ::: "memory");
    }

    auto load_kv = [&](int kt) {
        const float* kp = g_kqv + base + (size_t)(kt * BK) * E3_;
        const uint32_t kd = uKb + (uint32_t)(kt & 1) * KST * 4;
#pragma unroll
        for (int j = 0; j < 4; ++j) {
            const int i = tid + j * 256;
            const int n = i >> 4, c = (i & 15) << 2;
            cpa16(kd + (uint32_t)(n * 68 + c) * 4, kp + (size_t)n * E3_ + c);
        }
        const float* vp = kp + 2 * HD_;
        const uint32_t vd = uVt + (uint32_t)(kt % 3) * KST * 4;
#pragma unroll
        for (int j = 0; j < 16; ++j) {
            const int i = tid + j * 256;
            const int n = i & 63, d = i >> 6;
            cpa4(vd + (uint32_t)(d * 68 + n) * 4, vp + (size_t)n * E3_ + d);
        }
        asm volatile("cp.async.commit_group;" ::: "memory");
    };

    load_kv(0);

    asm volatile("cp.async.wait_group 1;" ::: "memory");  // Q stage done
    __syncthreads();

    // Q fragments in registers, scaled to log2 domain, re-rounded to tf32
    uint32_t qf[8][4];
    {
        const float* Pw = Pq + (w * 16) * 68;
#pragma unroll
        for (int ks = 0; ks < 8; ++ks) {
            const int k = ks * 8 + tig;
            qf[ks][0] = __float_as_uint(rtf(Pw[grp * 68 + k] * QSCALE));
            qf[ks][1] = __float_as_uint(rtf(Pw[(grp + 8) * 68 + k] * QSCALE));
            qf[ks][2] = __float_as_uint(rtf(Pw[grp * 68 + k + 4] * QSCALE));
            qf[ks][3] = __float_as_uint(rtf(Pw[(grp + 8) * 68 + k + 4] * QSCALE));
        }
    }
    __syncthreads();

    const int r0    = m0 + w * 16 + grp;
    const int r1    = r0 + 8;
    const int rmax  = m0 + w * 16 + 15;
    const int nt    = (m0 + BM) / BK;
    const int diag0 = m0 / BK;

    float oacc[8][4];
#pragma unroll
    for (int ni = 0; ni < 8; ++ni)
#pragma unroll
        for (int r = 0; r < 4; ++r) oacc[ni][r] = 0.f;
    float mr0 = NEG_INF, mr1 = NEG_INF, l0 = 0.f, l1 = 0.f;

    for (int kt = 0; kt < nt; ++kt) {
        asm volatile("cp.async.wait_group 0;" ::: "memory");
        __syncthreads();
        if (kt + 1 < nt) load_kv(kt + 1);

        const bool cur  = (kt * BK <= rmax);
        const bool prev = (kt > 0) && ((kt - 1) * BK <= rmax);

        float s[8][4];
        if (cur) {
            const uint32_t uKp = uKb + (uint32_t)(kt & 1) * KST * 4;
#pragma unroll
            for (int ni = 0; ni < 8; ++ni)
#pragma unroll
                for (int r = 0; r < 4; ++r) s[ni][r] = 0.f;
#pragma unroll
            for (int ks = 0; ks < 8; ++ks) {
                const int k = ks * 8;
                uint32_t bf[8][2];
#pragma unroll
                for (int np = 0; np < 4; ++np) {
                    uint32_t r[4];
                    ldsm4(r, uKp + (uint32_t)((np * 16 + lrB) * 68 + k + lcB) * 4);
                    bf[2 * np][0] = r[0]; bf[2 * np][1] = r[1];
                    bf[2 * np + 1][0] = r[2]; bf[2 * np + 1][1] = r[3];
                }
#pragma unroll
                for (int ni = 0; ni < 8; ++ni)
                    mma_tf32(s[ni], qf[ks], bf[ni]);
            }
        }

        // Deferred PV for tile kt-1 (tensor work independent of softmax(kt))
        if (prev) {
            const uint32_t uVp = uVt + (uint32_t)((kt - 1) % 3) * KST * 4;
            const uint32_t uPp = uPq + (uint32_t)((kt - 1) & 1) * PST * 4
                               + (uint32_t)(w * 16 + lrA) * 68 * 4;
#pragma unroll
            for (int ks = 0; ks < 8; ++ks) {
                const int k = ks * 8;
                uint32_t a[4];
                ldsm4(a, uPp + (uint32_t)(k + lcA) * 4);
                uint32_t bf[8][2];
#pragma unroll
                for (int np = 0; np < 4; ++np) {
                    uint32_t r[4];
                    ldsm4(r, uVp + (uint32_t)((np * 16 + lrB) * 68 + k + lcB) * 4);
                    bf[2 * np][0] = r[0]; bf[2 * np][1] = r[1];
                    bf[2 * np + 1][0] = r[2]; bf[2 * np + 1][1] = r[3];
                }
#pragma unroll
                for (int ni = 0; ni < 8; ++ni)
                    mma_tf32(oacc[ni], a, bf[ni]);
            }
        }

        if (cur) {
            // Causal mask (log2-domain scores)
            if (kt >= diag0) {
                const int colb = kt * BK;
#pragma unroll
                for (int ni = 0; ni < 8; ++ni) {
                    const int c = colb + ni * 8 + 2 * tig;
                    if (c > r0)     s[ni][0] = NEG_INF;
                    if (c + 1 > r0) s[ni][1] = NEG_INF;
                    if (c > r1)     s[ni][2] = NEG_INF;
                    if (c + 1 > r1) s[ni][3] = NEG_INF;
                }
            }

            float mx0 = NEG_INF, mx1 = NEG_INF;
#pragma unroll
            for (int ni = 0; ni < 8; ++ni) {
                mx0 = fmaxf(mx0, fmaxf(s[ni][0], s[ni][1]));
                mx1 = fmaxf(mx1, fmaxf(s[ni][2], s[ni][3]));
            }
            mx0 = fmaxf(mx0, __shfl_xor_sync(0xffffffffu, mx0, 1));
            mx0 = fmaxf(mx0, __shfl_xor_sync(0xffffffffu, mx0, 2));
            mx1 = fmaxf(mx1, __shfl_xor_sync(0xffffffffu, mx1, 1));
            mx1 = fmaxf(mx1, __shfl_xor_sync(0xffffffffu, mx1, 2));

            const float mn0 = fmaxf(mr0, mx0), mn1 = fmaxf(mr1, mx1);
            const float a0 = ex2(mr0 - mn0), a1 = ex2(mr1 - mn1);
            float sum0 = 0.f, sum1 = 0.f;
#pragma unroll
            for (int ni = 0; ni < 8; ++ni) {
                s[ni][0] = ex2(s[ni][0] - mn0);
                s[ni][1] = ex2(s[ni][1] - mn0);
                s[ni][2] = ex2(s[ni][2] - mn1);
                s[ni][3] = ex2(s[ni][3] - mn1);
                sum0 += s[ni][0] + s[ni][1];
                sum1 += s[ni][2] + s[ni][3];
            }
            sum0 += __shfl_xor_sync(0xffffffffu, sum0, 1);
            sum0 += __shfl_xor_sync(0xffffffffu, sum0, 2);
            sum1 += __shfl_xor_sync(0xffffffffu, sum1, 1);
            sum1 += __shfl_xor_sync(0xffffffffu, sum1, 2);

            l0 = l0 * a0 + sum0;  mr0 = mn0;
            l1 = l1 * a1 + sum1;  mr1 = mn1;
#pragma unroll
            for (int ni = 0; ni < 8; ++ni) {
                oacc[ni][0] *= a0; oacc[ni][1] *= a0;
                oacc[ni][2] *= a1; oacc[ni][3] *= a1;
            }

            // Store P (tf32-rounded) into this warp's strip, parity kt&1
            float* prow0 = Pq + (kt & 1) * PST + (w * 16 + grp) * 68;
            float* prow1 = prow0 + 8 * 68;
#pragma unroll
            for (int ni = 0; ni < 8; ++ni) {
                const int c = ni * 8 + 2 * tig;
                prow0[c]     = rtf(s[ni][0]);
                prow0[c + 1] = rtf(s[ni][1]);
                prow1[c]     = rtf(s[ni][2]);
                prow1[c + 1] = rtf(s[ni][3]);
            }
            __syncwarp();
        }
    }

    // Tail PV for the last tile (only warps whose last tile is nt-1: w >= 4)
    if ((nt - 1) * BK <= rmax) {
        const int kt = nt - 1;
        const uint32_t uVp = uVt + (uint32_t)(kt % 3) * KST * 4;
        const uint32_t uPp = uPq + (uint32_t)(kt & 1) * PST * 4
                           + (uint32_t)(w * 16 + lrA) * 68 * 4;
#pragma unroll
        for (int ks = 0; ks < 8; ++ks) {
            const int k = ks * 8;
            uint32_t a[4];
            ldsm4(a, uPp + (uint32_t)(k + lcA) * 4);
            uint32_t bf[8][2];
#pragma unroll
            for (int np = 0; np < 4; ++np) {
                uint32_t r[4];
                ldsm4(r, uVp + (uint32_t)((np * 16 + lrB) * 68 + k + lcB) * 4);
                bf[2 * np][0] = r[0]; bf[2 * np][1] = r[1];
                bf[2 * np + 1][0] = r[2]; bf[2 * np + 1][1] = r[3];
            }
#pragma unroll
            for (int ni = 0; ni < 8; ++ni)
                mma_tf32(oacc[ni], a, bf[ni]);
        }
    }

    // Epilogue: normalize, tf32-round (proj GEMM consumes g_sa), store
    const float inv0 = 1.0f / l0, inv1 = 1.0f / l1;
    float* d0 = g_sa + ((size_t)b * N_ + r0) * D_ + h * HD_;
    float* d1 = g_sa + ((size_t)b * N_ + r1) * D_ + h * HD_;
#pragma unroll
    for (int ni = 0; ni < 8; ++ni) {
        const int c = ni * 8 + 2 * tig;
        float2 o0, o1;
        o0.x = rtf(oacc[ni][0] * inv0); o0.y = rtf(oacc[ni][1] * inv0);
        o1.x = rtf(oacc[ni][2] * inv1); o1.y = rtf(oacc[ni][3] * inv1);
        *(float2*)(d0 + c) = o0;
        *(float2*)(d1 + c) = o1;
    }
}

// ---------------------------------------------------------------------------
extern "C" void kernel_launch(void* const* d_in, const int* in_sizes, int n_in,
                              void* d_out, int out_size)
{
    const float* x      = (const float*)d_in[0];
    const float* W_kqv  = (const float*)d_in[1];
    const float* b_kqv  = (const float*)d_in[2];
    const float* W_proj = (const float*)d_in[3];
    const float* b_proj = (const float*)d_in[4];
    float* out = (float*)d_out;

    const int SMEM_Q = (3 * 128 * 36 + 3 * E3_ * 36) * 4;   // 138240
    const int SMEM_P = (3 * 128 * 36 + 3 * 128 * 36) * 4;   // 110592
    const int SMEM_A = (5 * KST + 2 * PST) * 4;             // 156672
    cudaFuncSetAttribute(gemm_mma_kernel<E3_, 1>,
                         cudaFuncAttributeMaxDynamicSharedMemorySize, SMEM_Q);
    cudaFuncSetAttribute(gemm_mma_kernel<128, 0>,
                         cudaFuncAttributeMaxDynamicSharedMemorySize, SMEM_P);
    cudaFuncSetAttribute(attn_mma_kernel,
                         cudaFuncAttributeMaxDynamicSharedMemorySize, SMEM_A);

    rtf_x_kernel<<<MROWS * D_ / 1024, 256>>>(x);
    tr_kqv_kernel<<<dim3(D_ / 32, E3_ / 32, H_), dim3(32, 8)>>>(W_kqv);
    tr_proj_kernel<<<dim3(D_ / 32, D_ / 32), dim3(32, 8)>>>(W_proj);

    gemm_mma_kernel<E3_, 1><<<dim3(MROWS / 128, H_), 256, SMEM_Q>>>(b_kqv, nullptr);
    attn_mma_kernel<<<dim3(N_ / BM, H_, B_), 256, SMEM_A>>>();
    gemm_mma_kernel<128, 0><<<dim3(MROWS / 128, D_ / 128), 256, SMEM_P>>>(b_proj, out);
}

// round 9
// speedup vs baseline: 7.0722x; 2.3566x over previous
#include <cuda_runtime.h>
#include <cuda_fp16.h>
#include <cstdint>
#include <math.h>

// Problem constants
#define B_   4
#define N_   2048
#define D_   1024
#define H_   16
#define HD_  64
#define E3_  192          // 3 * head_dim, chunk order (k, q, v)
#define MROWS (B_ * N_)   // 8192

#define NEG_INF (-1e30f)
#define QSCALE (0.125f * 1.44269504088896f)   // 1/sqrt(64) * log2(e)

// Scratch (allocation-free rule: __device__ globals) — all fp16 operands
__device__ __half g_kqv[(size_t)B_ * H_ * N_ * E3_];   // [b][h][n][e]
__device__ __half g_sa [(size_t)B_ * N_ * D_];         // [b][n][h*hd+d]
__device__ __half g_xt [(size_t)MROWS * D_];           // x -> fp16
__device__ __half g_wt_kqv[(size_t)H_ * E3_ * D_];     // W_kqv^T [h][e][k]
__device__ __half g_wt_proj[(size_t)D_ * D_];          // W_proj^T [n][k]

// ---------------------------------------------------------------------------
// Helpers
// ---------------------------------------------------------------------------
__device__ __forceinline__ float ex2(float x) {
    float y;
    asm("ex2.approx.f32 %0, %1;" : "=f"(y) : "f"(x));
    return y;
}
__device__ __forceinline__ void cpa16(uint32_t dst, const void* src) {
    asm volatile("cp.async.ca.shared.global [%0], [%1], 16;" :: "r"(dst), "l"(src));
}
__device__ __forceinline__ uint32_t smem_u32(const void* p) {
    uint32_t a;
    asm("{ .reg .u64 t; cvta.to.shared.u64 t, %1; cvt.u32.u64 %0, t; }"
        : "=r"(a) : "l"(p));
    return a;
}
// fp16 mma, fp32 accumulate
__device__ __forceinline__ void mma_f16(float* c, const uint32_t* a, const uint32_t* b) {
    asm volatile(
        "mma.sync.aligned.m16n8k16.row.col.f32.f16.f16.f32 "
        "{%0,%1,%2,%3}, {%4,%5,%6,%7}, {%8,%9}, {%0,%1,%2,%3};"
        : "+f"(c[0]), "+f"(c[1]), "+f"(c[2]), "+f"(c[3])
        : "r"(a[0]), "r"(a[1]), "r"(a[2]), "r"(a[3]), "r"(b[0]), "r"(b[1]));
}
__device__ __forceinline__ void ldsm4(uint32_t* r, uint32_t addr) {
    asm volatile(
        "ldmatrix.sync.aligned.m8n8.x4.shared.b16 {%0,%1,%2,%3}, [%4];"
        : "=r"(r[0]), "=r"(r[1]), "=r"(r[2]), "=r"(r[3]) : "r"(addr));
}
__device__ __forceinline__ void ldsm4t(uint32_t* r, uint32_t addr) {
    asm volatile(
        "ldmatrix.sync.aligned.m8n8.x4.trans.shared.b16 {%0,%1,%2,%3}, [%4];"
        : "=r"(r[0]), "=r"(r[1]), "=r"(r[2]), "=r"(r[3]) : "r"(addr));
}

// ---------------------------------------------------------------------------
// Prep kernels: fp16-convert x; transpose+convert weights to [n][k]
// ---------------------------------------------------------------------------
__global__ void h_x_kernel(const float* __restrict__ x) {
    size_t i = ((size_t)blockIdx.x * 256 + threadIdx.x) * 4;
    float4 v = *(const float4*)(x + i);
    __half2* dst = (__half2*)(g_xt + i);
    dst[0] = __floats2half2_rn(v.x, v.y);
    dst[1] = __floats2half2_rn(v.z, v.w);
}

__global__ void tr_kqv_kernel(const float* __restrict__ W) {
    __shared__ float t[32][33];
    const int h = blockIdx.z, k0 = blockIdx.x * 32, e0 = blockIdx.y * 32;
    const float* Wh = W + (size_t)h * D_ * E3_;
    __half* Wt = g_wt_kqv + (size_t)h * E3_ * D_;
    const int x = threadIdx.x, y = threadIdx.y;
#pragma unroll
    for (int j = 0; j < 32; j += 8)
        t[y + j][x] = Wh[(size_t)(k0 + y + j) * E3_ + e0 + x];
    __syncthreads();
#pragma unroll
    for (int j = 0; j < 32; j += 8)
        Wt[(size_t)(e0 + y + j) * D_ + k0 + x] = __float2half_rn(t[x][y + j]);
}

__global__ void tr_proj_kernel(const float* __restrict__ W) {
    __shared__ float t[32][33];
    const int k0 = blockIdx.x * 32, n0 = blockIdx.y * 32;
    const int x = threadIdx.x, y = threadIdx.y;
#pragma unroll
    for (int j = 0; j < 32; j += 8)
        t[y + j][x] = W[(size_t)(k0 + y + j) * D_ + n0 + x];
    __syncthreads();
#pragma unroll
    for (int j = 0; j < 32; j += 8)
        g_wt_proj[(size_t)(n0 + y + j) * D_ + k0 + x] = __float2half_rn(t[x][y + j]);
}

// ---------------------------------------------------------------------------
// fp16 mma GEMM. CTA tile 128 x NT, K=1024 in chunks of 64 halves.
// 3-stage cp.async ring, one __syncthreads per chunk, ldmatrix frag loads.
// Smem row stride 72 halves (144B): 16B-aligned rows, ldmatrix conflict-free.
// ---------------------------------------------------------------------------
template <int NT, int PER_HEAD>
__global__ __launch_bounds__(256, 1) void gemm_mma_kernel(
    const float* __restrict__ bias, float* __restrict__ Cout)
{
    constexpr int NSUB = NT / 32;        // 8-wide n-subtiles per warp
    constexpr int AST = 128 * 72;        // halves per A stage
    constexpr int BST = NT * 72;
    extern __shared__ __half smh[];
    __half* As = smh;                    // [3][AST]
    __half* Bs = smh + 3 * AST;          // [3][BST]

    const int tid  = threadIdx.x;
    const int m0   = blockIdx.x * 128;
    const int head = blockIdx.y;
    const int n0   = PER_HEAD ? 0 : blockIdx.y * NT;

    const __half* Ab = (PER_HEAD ? g_xt : g_sa) + (size_t)m0 * D_;
    const __half* Bt = PER_HEAD ? (g_wt_kqv + (size_t)head * E3_ * D_)
                                : (g_wt_proj + (size_t)n0 * D_);

    const uint32_t sA = smem_u32(As);
    const uint32_t sB = smem_u32(Bs);

    auto load_stage = [&](int kc, int buf) {
        const __half* ap = Ab + kc * 64;
        const uint32_t da = sA + (uint32_t)buf * AST * 2;
#pragma unroll
        for (int j = 0; j < 4; ++j) {                 // 128 rows x 8 x 16B
            const int idx = tid + j * 256;
            const int r = idx >> 3, q = (idx & 7) << 3;
            cpa16(da + (uint32_t)(r * 72 + q) * 2, ap + (size_t)r * D_ + q);
        }
        const __half* bp = Bt + kc * 64;
        const uint32_t db = sB + (uint32_t)buf * BST * 2;
#pragma unroll
        for (int j = 0; j < NT / 32; ++j) {           // NT rows x 8 x 16B
            const int idx = tid + j * 256;
            const int r = idx >> 3, q = (idx & 7) << 3;
            cpa16(db + (uint32_t)(r * 72 + q) * 2, bp + (size_t)r * D_ + q);
        }
    };

    const int w    = tid >> 5, lane = tid & 31;
    const int wm   = (w & 1) * 64;
    const int wn   = (w >> 1) * NSUB * 8;
    const int grp  = lane >> 2, tig = lane & 3;

    // ldmatrix lane->address mappings (b16, 8-half col steps)
    const int lrA = ((lane >> 3) & 1) * 8 + (lane & 7);
    const int lcA = ((lane >> 4) & 1) * 8;
    const int lrB = ((lane >> 4) & 1) * 8 + (lane & 7);
    const int lcB = ((lane >> 3) & 1) * 8;

    float acc[4][NSUB][4];
#pragma unroll
    for (int mi = 0; mi < 4; ++mi)
#pragma unroll
        for (int ni = 0; ni < NSUB; ++ni)
#pragma unroll
            for (int r = 0; r < 4; ++r) acc[mi][ni][r] = 0.f;

    load_stage(0, 0);
    asm volatile("cp.async.commit_group;" ::: "memory");
    load_stage(1, 1);
    asm volatile("cp.async.commit_group;" ::: "memory");

    for (int kc = 0; kc < 16; ++kc) {
        asm volatile("cp.async.wait_group 1;" ::: "memory");
        __syncthreads();
        if (kc + 2 < 16) load_stage(kc + 2, (kc + 2) % 3);
        asm volatile("cp.async.commit_group;" ::: "memory");

        const int st = kc % 3;
        const uint32_t uAp = sA + (uint32_t)st * AST * 2;
        const uint32_t uBp = sB + (uint32_t)st * BST * 2;
#pragma unroll
        for (int ks = 0; ks < 4; ++ks) {              // 4 x k16 = 64 halves
            const int k = ks * 16;
            uint32_t a[4][4], bf[NSUB][2];
#pragma unroll
            for (int mi = 0; mi < 4; ++mi)
                ldsm4(a[mi], uAp + (uint32_t)((wm + mi * 16 + lrA) * 72 + k + lcA) * 2);
#pragma unroll
            for (int np = 0; np < NSUB / 2; ++np) {
                uint32_t r[4];
                ldsm4(r, uBp + (uint32_t)((wn + np * 16 + lrB) * 72 + k + lcB) * 2);
                bf[2 * np][0] = r[0]; bf[2 * np][1] = r[1];
                bf[2 * np + 1][0] = r[2]; bf[2 * np + 1][1] = r[3];
            }
#pragma unroll
            for (int mi = 0; mi < 4; ++mi)
#pragma unroll
                for (int ni = 0; ni < NSUB; ++ni)
                    mma_f16(acc[mi][ni], a[mi], bf[ni]);
        }
    }

#pragma unroll
    for (int mi = 0; mi < 4; ++mi) {
        const int mbase = m0 + wm + mi * 16 + grp;
#pragma unroll
        for (int half = 0; half < 2; ++half) {
            const int m = mbase + half * 8;
#pragma unroll
            for (int ni = 0; ni < NSUB; ++ni) {
                const int c = wn + ni * 8 + 2 * tig;
                const float vx = acc[mi][ni][half * 2 + 0];
                const float vy = acc[mi][ni][half * 2 + 1];
                if (PER_HEAD) {
                    const int b = m >> 11, tok = m & 2047;
                    __half* dst = g_kqv + (((size_t)b * H_ + head) * N_ + tok) * E3_;
                    const float* bsp = bias + head * E3_;
                    *(__half2*)(dst + c) =
                        __floats2half2_rn(vx + bsp[c], vy + bsp[c + 1]);
                } else {
                    float* dst = Cout + (size_t)m * D_ + n0;
                    const float* bsp = bias + n0;
                    float2 o; o.x = vx + bsp[c]; o.y = vy + bsp[c + 1];
                    *(float2*)(dst + c) = o;
                }
            }
        }
    }
}

// ---------------------------------------------------------------------------
// fp16 tensor-core causal flash attention with deferred-PV pipeline.
// CTA = 128 queries of one (b,h); 8 warps x 16-row strips; key tiles of 64.
// K,V tiles stored natural [key][d] (V transposed for free by ldmatrix.trans).
// Log2-domain softmax: scale folded into the subtract as one FFMA.
// ---------------------------------------------------------------------------
#define BM 128
#define BK 64
#define KSTH (64 * 72)     // K or V tile (halves)
#define PSTH (128 * 72)    // Q/P buffer (halves)

__global__ __launch_bounds__(256, 1) void attn_mma_kernel()
{
    extern __shared__ __half smh[];
    __half* Kb = smh;                  // [2][KSTH]  K tiles [key][d]
    __half* Vb = smh + 2 * KSTH;       // [3][KSTH]  V tiles [key][d]
    __half* Pq = smh + 5 * KSTH;       // [2][PSTH]  P strips (buf0 = Q stage)

    const int qi  = (int)(gridDim.x - 1 - blockIdx.x);  // heavy tiles first
    const int h   = blockIdx.y, b = blockIdx.z;
    const int tid = threadIdx.x;
    const int w   = tid >> 5, lane = tid & 31;
    const int grp = lane >> 2, tig = lane & 3;
    const int m0  = qi * BM;
    const size_t base = ((size_t)b * H_ + h) * N_ * E3_;

    const uint32_t uKb = smem_u32(Kb);
    const uint32_t uVb = smem_u32(Vb);
    const uint32_t uPq = smem_u32(Pq);

    const int lrA = ((lane >> 3) & 1) * 8 + (lane & 7);
    const int lcA = ((lane >> 4) & 1) * 8;
    const int lrB = ((lane >> 4) & 1) * 8 + (lane & 7);
    const int lcB = ((lane >> 3) & 1) * 8;

    // Stage Q (128 x 64 halves) into Pq buffer 0
    {
        const __half* q0 = g_kqv + base + (size_t)m0 * E3_ + HD_;
#pragma unroll
        for (int j = 0; j < 4; ++j) {
            const int i = tid + j * 256;
            const int r = i >> 3, c = (i & 7) << 3;
            cpa16(uPq + (uint32_t)(r * 72 + c) * 2, q0 + (size_t)r * E3_ + c);
        }
        asm volatile("cp.async.commit_group;" ::: "memory");
    }

    auto load_kv = [&](int kt) {
        const __half* kp = g_kqv + base + (size_t)(kt * BK) * E3_;
        const uint32_t kd = uKb + (uint32_t)(kt & 1) * KSTH * 2;
#pragma unroll
        for (int j = 0; j < 2; ++j) {
            const int i = tid + j * 256;
            const int n = i >> 3, c = (i & 7) << 3;
            cpa16(kd + (uint32_t)(n * 72 + c) * 2, kp + (size_t)n * E3_ + c);
        }
        const __half* vp = kp + 2 * HD_;
        const uint32_t vd = uVb + (uint32_t)(kt % 3) * KSTH * 2;
#pragma unroll
        for (int j = 0; j < 2; ++j) {
            const int i = tid + j * 256;
            const int n = i >> 3, c = (i & 7) << 3;
            cpa16(vd + (uint32_t)(n * 72 + c) * 2, vp + (size_t)n * E3_ + c);
        }
        asm volatile("cp.async.commit_group;" ::: "memory");
    };

    load_kv(0);

    asm volatile("cp.async.wait_group 1;" ::: "memory");  // Q stage done
    __syncthreads();

    // Q fragments (unscaled) in registers for the whole kernel
    uint32_t qf[4][4];
    {
        const uint32_t uQw = uPq + (uint32_t)((w * 16 + lrA) * 72) * 2;
#pragma unroll
        for (int ks = 0; ks < 4; ++ks)
            ldsm4(qf[ks], uQw + (uint32_t)(ks * 16 + lcA) * 2);
    }
    __syncthreads();

    const int r0    = m0 + w * 16 + grp;
    const int r1    = r0 + 8;
    const int rmax  = m0 + w * 16 + 15;
    const int nt    = (m0 + BM) / BK;
    const int diag0 = m0 / BK;

    float oacc[8][4];
#pragma unroll
    for (int ni = 0; ni < 8; ++ni)
#pragma unroll
        for (int r = 0; r < 4; ++r) oacc[ni][r] = 0.f;
    float mr0 = NEG_INF, mr1 = NEG_INF, l0 = 0.f, l1 = 0.f;

    for (int kt = 0; kt < nt; ++kt) {
        asm volatile("cp.async.wait_group 0;" ::: "memory");
        __syncthreads();
        if (kt + 1 < nt) load_kv(kt + 1);

        const bool cur  = (kt * BK <= rmax);
        const bool prev = (kt > 0) && ((kt - 1) * BK <= rmax);

        float s[8][4];
        if (cur) {
            const uint32_t uKp = uKb + (uint32_t)(kt & 1) * KSTH * 2;
#pragma unroll
            for (int ni = 0; ni < 8; ++ni)
#pragma unroll
                for (int r = 0; r < 4; ++r) s[ni][r] = 0.f;
#pragma unroll
            for (int ks = 0; ks < 4; ++ks) {
                const int k = ks * 16;
                uint32_t bf[8][2];
#pragma unroll
                for (int np = 0; np < 4; ++np) {
                    uint32_t r[4];
                    ldsm4(r, uKp + (uint32_t)((np * 16 + lrB) * 72 + k + lcB) * 2);
                    bf[2 * np][0] = r[0]; bf[2 * np][1] = r[1];
                    bf[2 * np + 1][0] = r[2]; bf[2 * np + 1][1] = r[3];
                }
#pragma unroll
                for (int ni = 0; ni < 8; ++ni)
                    mma_f16(s[ni], qf[ks], bf[ni]);
            }
        }

        // Deferred PV for tile kt-1 (independent of softmax(kt))
        if (prev) {
            const uint32_t uVp = uVb + (uint32_t)((kt - 1) % 3) * KSTH * 2;
            const uint32_t uPp = uPq + (uint32_t)((kt - 1) & 1) * PSTH * 2
                               + (uint32_t)((w * 16 + lrA) * 72) * 2;
#pragma unroll
            for (int ks = 0; ks < 4; ++ks) {          // k = key index
                const int k = ks * 16;
                uint32_t a[4];
                ldsm4(a, uPp + (uint32_t)(k + lcA) * 2);
                uint32_t bf[8][2];
#pragma unroll
                for (int np = 0; np < 4; ++np) {      // n = d index, via trans
                    uint32_t r[4];
                    ldsm4t(r, uVp + (uint32_t)((k + lrA) * 72 + np * 16 + lcA) * 2);
                    bf[2 * np][0] = r[0]; bf[2 * np][1] = r[1];
                    bf[2 * np + 1][0] = r[2]; bf[2 * np + 1][1] = r[3];
                }
#pragma unroll
                for (int ni = 0; ni < 8; ++ni)
                    mma_f16(oacc[ni], a, bf[ni]);
            }
        }

        if (cur) {
            // Causal mask on raw scores
            if (kt >= diag0) {
                const int colb = kt * BK;
#pragma unroll
                for (int ni = 0; ni < 8; ++ni) {
                    const int c = colb + ni * 8 + 2 * tig;
                    if (c > r0)     s[ni][0] = NEG_INF;
                    if (c + 1 > r0) s[ni][1] = NEG_INF;
                    if (c > r1)     s[ni][2] = NEG_INF;
                    if (c + 1 > r1) s[ni][3] = NEG_INF;
                }
            }

            float mx0 = NEG_INF, mx1 = NEG_INF;
#pragma unroll
            for (int ni = 0; ni < 8; ++ni) {
                mx0 = fmaxf(mx0, fmaxf(s[ni][0], s[ni][1]));
                mx1 = fmaxf(mx1, fmaxf(s[ni][2], s[ni][3]));
            }
            mx0 = fmaxf(mx0, __shfl_xor_sync(0xffffffffu, mx0, 1));
            mx0 = fmaxf(mx0, __shfl_xor_sync(0xffffffffu, mx0, 2));
            mx1 = fmaxf(mx1, __shfl_xor_sync(0xffffffffu, mx1, 1));
            mx1 = fmaxf(mx1, __shfl_xor_sync(0xffffffffu, mx1, 2));

            // scaled (log2) domain maxima
            const float mn0 = fmaxf(mr0, mx0 * QSCALE);
            const float mn1 = fmaxf(mr1, mx1 * QSCALE);
            const float a0 = ex2(mr0 - mn0), a1 = ex2(mr1 - mn1);
            float sum0 = 0.f, sum1 = 0.f;
#pragma unroll
            for (int ni = 0; ni < 8; ++ni) {
                s[ni][0] = ex2(fmaf(s[ni][0], QSCALE, -mn0));
                s[ni][1] = ex2(fmaf(s[ni][1], QSCALE, -mn0));
                s[ni][2] = ex2(fmaf(s[ni][2], QSCALE, -mn1));
                s[ni][3] = ex2(fmaf(s[ni][3], QSCALE, -mn1));
                sum0 += s[ni][0] + s[ni][1];
                sum1 += s[ni][2] + s[ni][3];
            }
            sum0 += __shfl_xor_sync(0xffffffffu, sum0, 1);
            sum0 += __shfl_xor_sync(0xffffffffu, sum0, 2);
            sum1 += __shfl_xor_sync(0xffffffffu, sum1, 1);
            sum1 += __shfl_xor_sync(0xffffffffu, sum1, 2);

            l0 = l0 * a0 + sum0;  mr0 = mn0;
            l1 = l1 * a1 + sum1;  mr1 = mn1;
#pragma unroll
            for (int ni = 0; ni < 8; ++ni) {
                oacc[ni][0] *= a0; oacc[ni][1] *= a0;
                oacc[ni][2] *= a1; oacc[ni][3] *= a1;
            }

            // Store P (fp16) into this warp's strip, parity kt&1
            __half* prow0 = Pq + (kt & 1) * PSTH + (w * 16 + grp) * 72;
            __half* prow1 = prow0 + 8 * 72;
#pragma unroll
            for (int ni = 0; ni < 8; ++ni) {
                const int c = ni * 8 + 2 * tig;
                *(__half2*)(prow0 + c) = __floats2half2_rn(s[ni][0], s[ni][1]);
                *(__half2*)(prow1 + c) = __floats2half2_rn(s[ni][2], s[ni][3]);
            }
            __syncwarp();
        }
    }

    // Tail PV for the last tile
    if ((nt - 1) * BK <= rmax) {
        const int kt = nt - 1;
        const uint32_t uVp = uVb + (uint32_t)(kt % 3) * KSTH * 2;
        const uint32_t uPp = uPq + (uint32_t)(kt & 1) * PSTH * 2
                           + (uint32_t)((w * 16 + lrA) * 72) * 2;
#pragma unroll
        for (int ks = 0; ks < 4; ++ks) {
            const int k = ks * 16;
            uint32_t a[4];
            ldsm4(a, uPp + (uint32_t)(k + lcA) * 2);
            uint32_t bf[8][2];
#pragma unroll
            for (int np = 0; np < 4; ++np) {
                uint32_t r[4];
                ldsm4t(r, uVp + (uint32_t)((k + lrA) * 72 + np * 16 + lcA) * 2);
                bf[2 * np][0] = r[0]; bf[2 * np][1] = r[1];
                bf[2 * np + 1][0] = r[2]; bf[2 * np + 1][1] = r[3];
            }
#pragma unroll
            for (int ni = 0; ni < 8; ++ni)
                mma_f16(oacc[ni], a, bf[ni]);
        }
    }

    // Epilogue: normalize, fp16-store (proj GEMM consumes g_sa)
    const float inv0 = 1.0f / l0, inv1 = 1.0f / l1;
    __half* d0 = g_sa + ((size_t)b * N_ + r0) * D_ + h * HD_;
    __half* d1 = g_sa + ((size_t)b * N_ + r1) * D_ + h * HD_;
#pragma unroll
    for (int ni = 0; ni < 8; ++ni) {
        const int c = ni * 8 + 2 * tig;
        *(__half2*)(d0 + c) = __floats2half2_rn(oacc[ni][0] * inv0, oacc[ni][1] * inv0);
        *(__half2*)(d1 + c) = __floats2half2_rn(oacc[ni][2] * inv1, oacc[ni][3] * inv1);
    }
}

// ---------------------------------------------------------------------------
extern "C" void kernel_launch(void* const* d_in, const int* in_sizes, int n_in,
                              void* d_out, int out_size)
{
    const float* x      = (const float*)d_in[0];
    const float* W_kqv  = (const float*)d_in[1];
    const float* b_kqv  = (const float*)d_in[2];
    const float* W_proj = (const float*)d_in[3];
    const float* b_proj = (const float*)d_in[4];
    float* out = (float*)d_out;

    const int SMEM_Q = 3 * (128 + E3_) * 72 * 2;   // 138240
    const int SMEM_P = 3 * (128 + 128) * 72 * 2;   // 110592
    const int SMEM_A = (5 * KSTH + 2 * PSTH) * 2;  // 82944
    cudaFuncSetAttribute(gemm_mma_kernel<E3_, 1>,
                         cudaFuncAttributeMaxDynamicSharedMemorySize, SMEM_Q);
    cudaFuncSetAttribute(gemm_mma_kernel<128, 0>,
                         cudaFuncAttributeMaxDynamicSharedMemorySize, SMEM_P);
    cudaFuncSetAttribute(attn_mma_kernel,
                         cudaFuncAttributeMaxDynamicSharedMemorySize, SMEM_A);

    h_x_kernel<<<MROWS * D_ / 1024, 256>>>(x);
    tr_kqv_kernel<<<dim3(D_ / 32, E3_ / 32, H_), dim3(32, 8)>>>(W_kqv);
    tr_proj_kernel<<<dim3(D_ / 32, D_ / 32), dim3(32, 8)>>>(W_proj);

    gemm_mma_kernel<E3_, 1><<<dim3(MROWS / 128, H_), 256, SMEM_Q>>>(b_kqv, nullptr);
    attn_mma_kernel<<<dim3(N_ / BM, H_, B_), 256, SMEM_A>>>();
    gemm_mma_kernel<128, 0><<<dim3(MROWS / 128, D_ / 128), 256, SMEM_P>>>(b_proj, out);
}

// round 11
// speedup vs baseline: 7.1814x; 1.0154x over previous
#include <cuda_runtime.h>
#include <cuda_fp16.h>
#include <cstdint>
#include <math.h>

// Problem constants
#define B_   4
#define N_   2048
#define D_   1024
#define H_   16
#define HD_  64
#define E3_  192          // 3 * head_dim, chunk order (k, q, v)
#define MROWS (B_ * N_)   // 8192

#define NEG_INF (-1e30f)
#define QSCALE (0.125f * 1.44269504088896f)   // 1/sqrt(64) * log2(e)

// Scratch (allocation-free rule: __device__ globals) — all fp16 operands
__device__ __half g_kqv[(size_t)B_ * H_ * N_ * E3_];   // [b][h][n][e]
__device__ __half g_sa [(size_t)B_ * N_ * D_];         // [b][n][h*hd+d]
__device__ __half g_xt [(size_t)MROWS * D_];           // x -> fp16
__device__ __half g_wt_kqv[(size_t)H_ * E3_ * D_];     // W_kqv^T [h][e][k]
__device__ __half g_wt_proj[(size_t)D_ * D_];          // W_proj^T [n][k]

// ---------------------------------------------------------------------------
// Helpers
// ---------------------------------------------------------------------------
__device__ __forceinline__ float ex2(float x) {
    float y;
    asm("ex2.approx.f32 %0, %1;" : "=f"(y) : "f"(x));
    return y;
}
__device__ __forceinline__ void cpa16(uint32_t dst, const void* src) {
    asm volatile("cp.async.ca.shared.global [%0], [%1], 16;" :: "r"(dst), "l"(src));
}
__device__ __forceinline__ uint32_t smem_u32(const void* p) {
    uint32_t a;
    asm("{ .reg .u64 t; cvta.to.shared.u64 t, %1; cvt.u32.u64 %0, t; }"
        : "=r"(a) : "l"(p));
    return a;
}
__device__ __forceinline__ void mma_f16(float* c, const uint32_t* a, const uint32_t* b) {
    asm volatile(
        "mma.sync.aligned.m16n8k16.row.col.f32.f16.f16.f32 "
        "{%0,%1,%2,%3}, {%4,%5,%6,%7}, {%8,%9}, {%0,%1,%2,%3};"
        : "+f"(c[0]), "+f"(c[1]), "+f"(c[2]), "+f"(c[3])
        : "r"(a[0]), "r"(a[1]), "r"(a[2]), "r"(a[3]), "r"(b[0]), "r"(b[1]));
}
__device__ __forceinline__ void ldsm4(uint32_t* r, uint32_t addr) {
    asm volatile(
        "ldmatrix.sync.aligned.m8n8.x4.shared.b16 {%0,%1,%2,%3}, [%4];"
        : "=r"(r[0]), "=r"(r[1]), "=r"(r[2]), "=r"(r[3]) : "r"(addr));
}
__device__ __forceinline__ void ldsm4t(uint32_t* r, uint32_t addr) {
    asm volatile(
        "ldmatrix.sync.aligned.m8n8.x4.trans.shared.b16 {%0,%1,%2,%3}, [%4];"
        : "=r"(r[0]), "=r"(r[1]), "=r"(r[2]), "=r"(r[3]) : "r"(addr));
}
__device__ __forceinline__ void mbar_wait(uint32_t mbar, uint32_t parity) {
    uint32_t done;
    asm volatile(
        "{\n\t.reg .pred p;\n\t"
        "mbarrier.try_wait.parity.acquire.cta.shared::cta.b64 p, [%1], %2;\n\t"
        "selp.b32 %0, 1, 0, p;\n\t}"
        : "=r"(done) : "r"(mbar), "r"(parity) : "memory");
    while (!done) {
        asm volatile(
            "{\n\t.reg .pred p;\n\t"
            "mbarrier.try_wait.parity.acquire.cta.shared::cta.b64 p, [%1], %2, 0x989680;\n\t"
            "selp.b32 %0, 1, 0, p;\n\t}"
            : "=r"(done) : "r"(mbar), "r"(parity) : "memory");
    }
}

// ---------------------------------------------------------------------------
// Merged prep kernel: fp16-convert x + transpose/convert both weights.
// ---------------------------------------------------------------------------
#define PREP_X   (MROWS * D_ / 1024)          // 8192 blocks
#define PREP_KQV (32 * (E3_ / 32) * H_)       // 3072 blocks
#define PREP_PRJ (32 * 32)                    // 1024 blocks

__global__ void prep_kernel(const float* __restrict__ x,
                            const float* __restrict__ Wkqv,
                            const float* __restrict__ Wproj)
{
    __shared__ float t[32][33];
    const int bx = blockIdx.x, tid = threadIdx.x;
    if (bx < PREP_X) {
        size_t i = ((size_t)bx * 256 + tid) * 4;
        float4 v = *(const float4*)(x + i);
        __half2* dst = (__half2*)(g_xt + i);
        dst[0] = __floats2half2_rn(v.x, v.y);
        dst[1] = __floats2half2_rn(v.z, v.w);
    } else if (bx < PREP_X + PREP_KQV) {
        const int bid = bx - PREP_X;
        const int k0 = (bid & 31) * 32;
        const int e0 = ((bid >> 5) % (E3_ / 32)) * 32;
        const int h  = bid / (32 * (E3_ / 32));
        const float* Wh = Wkqv + (size_t)h * D_ * E3_;
        __half* Wt = g_wt_kqv + (size_t)h * E3_ * D_;
        const int xx = tid & 31, yy = tid >> 5;
#pragma unroll
        for (int j = 0; j < 32; j += 8)
            t[yy + j][xx] = Wh[(size_t)(k0 + yy + j) * E3_ + e0 + xx];
        __syncthreads();
#pragma unroll
        for (int j = 0; j < 32; j += 8)
            Wt[(size_t)(e0 + yy + j) * D_ + k0 + xx] = __float2half_rn(t[xx][yy + j]);
    } else {
        const int bid = bx - PREP_X - PREP_KQV;
        const int k0 = (bid & 31) * 32;
        const int n0 = (bid >> 5) * 32;
        const int xx = tid & 31, yy = tid >> 5;
#pragma unroll
        for (int j = 0; j < 32; j += 8)
            t[yy + j][xx] = Wproj[(size_t)(k0 + yy + j) * D_ + n0 + xx];
        __syncthreads();
#pragma unroll
        for (int j = 0; j < 32; j += 8)
            g_wt_proj[(size_t)(n0 + yy + j) * D_ + k0 + xx] = __float2half_rn(t[xx][yy + j]);
    }
}

// ---------------------------------------------------------------------------
// fp16 mma GEMM. CTA tile 128 x NT, K=1024 in chunks of 64 halves.
// 3-stage cp.async ring, one __syncthreads per chunk, ldmatrix frag loads.
// ---------------------------------------------------------------------------
template <int NT, int PER_HEAD>
__global__ __launch_bounds__(256, 1) void gemm_mma_kernel(
    const float* __restrict__ bias, float* __restrict__ Cout)
{
    constexpr int NSUB = NT / 32;
    constexpr int AST = 128 * 72;
    constexpr int BST = NT * 72;
    extern __shared__ __half smh[];
    __half* As = smh;
    __half* Bs = smh + 3 * AST;

    const int tid  = threadIdx.x;
    const int m0   = blockIdx.x * 128;
    const int head = blockIdx.y;
    const int n0   = PER_HEAD ? 0 : blockIdx.y * NT;

    const __half* Ab = (PER_HEAD ? g_xt : g_sa) + (size_t)m0 * D_;
    const __half* Bt = PER_HEAD ? (g_wt_kqv + (size_t)head * E3_ * D_)
                                : (g_wt_proj + (size_t)n0 * D_);

    const uint32_t sA = smem_u32(As);
    const uint32_t sB = smem_u32(Bs);

    auto load_stage = [&](int kc, int buf) {
        const __half* ap = Ab + kc * 64;
        const uint32_t da = sA + (uint32_t)buf * AST * 2;
#pragma unroll
        for (int j = 0; j < 4; ++j) {
            const int idx = tid + j * 256;
            const int r = idx >> 3, q = (idx & 7) << 3;
            cpa16(da + (uint32_t)(r * 72 + q) * 2, ap + (size_t)r * D_ + q);
        }
        const __half* bp = Bt + kc * 64;
        const uint32_t db = sB + (uint32_t)buf * BST * 2;
#pragma unroll
        for (int j = 0; j < NT / 32; ++j) {
            const int idx = tid + j * 256;
            const int r = idx >> 3, q = (idx & 7) << 3;
            cpa16(db + (uint32_t)(r * 72 + q) * 2, bp + (size_t)r * D_ + q);
        }
    };

    const int w    = tid >> 5, lane = tid & 31;
    const int wm   = (w & 1) * 64;
    const int wn   = (w >> 1) * NSUB * 8;
    const int grp  = lane >> 2, tig = lane & 3;

    const int lrA = ((lane >> 3) & 1) * 8 + (lane & 7);
    const int lcA = ((lane >> 4) & 1) * 8;
    const int lrB = ((lane >> 4) & 1) * 8 + (lane & 7);
    const int lcB = ((lane >> 3) & 1) * 8;

    float acc[4][NSUB][4];
#pragma unroll
    for (int mi = 0; mi < 4; ++mi)
#pragma unroll
        for (int ni = 0; ni < NSUB; ++ni)
#pragma unroll
            for (int r = 0; r < 4; ++r) acc[mi][ni][r] = 0.f;

    load_stage(0, 0);
    asm volatile("cp.async.commit_group;" ::: "memory");
    load_stage(1, 1);
    asm volatile("cp.async.commit_group;" ::: "memory");

    for (int kc = 0; kc < 16; ++kc) {
        asm volatile("cp.async.wait_group 1;" ::: "memory");
        __syncthreads();
        if (kc + 2 < 16) load_stage(kc + 2, (kc + 2) % 3);
        asm volatile("cp.async.commit_group;" ::: "memory");

        const int st = kc % 3;
        const uint32_t uAp = sA + (uint32_t)st * AST * 2;
        const uint32_t uBp = sB + (uint32_t)st * BST * 2;
#pragma unroll
        for (int ks = 0; ks < 4; ++ks) {
            const int k = ks * 16;
            uint32_t a[4][4], bf[NSUB][2];
#pragma unroll
            for (int mi = 0; mi < 4; ++mi)
                ldsm4(a[mi], uAp + (uint32_t)((wm + mi * 16 + lrA) * 72 + k + lcA) * 2);
#pragma unroll
            for (int np = 0; np < NSUB / 2; ++np) {
                uint32_t r[4];
                ldsm4(r, uBp + (uint32_t)((wn + np * 16 + lrB) * 72 + k + lcB) * 2);
                bf[2 * np][0] = r[0]; bf[2 * np][1] = r[1];
                bf[2 * np + 1][0] = r[2]; bf[2 * np + 1][1] = r[3];
            }
#pragma unroll
            for (int mi = 0; mi < 4; ++mi)
#pragma unroll
                for (int ni = 0; ni < NSUB; ++ni)
                    mma_f16(acc[mi][ni], a[mi], bf[ni]);
        }
    }

#pragma unroll
    for (int mi = 0; mi < 4; ++mi) {
        const int mbase = m0 + wm + mi * 16 + grp;
#pragma unroll
        for (int half = 0; half < 2; ++half) {
            const int m = mbase + half * 8;
#pragma unroll
            for (int ni = 0; ni < NSUB; ++ni) {
                const int c = wn + ni * 8 + 2 * tig;
                const float vx = acc[mi][ni][half * 2 + 0];
                const float vy = acc[mi][ni][half * 2 + 1];
                if (PER_HEAD) {
                    const int b = m >> 11, tok = m & 2047;
                    __half* dst = g_kqv + (((size_t)b * H_ + head) * N_ + tok) * E3_;
                    const float* bsp = bias + head * E3_;
                    *(__half2*)(dst + c) =
                        __floats2half2_rn(vx + bsp[c], vy + bsp[c + 1]);
                } else {
                    float* dst = Cout + (size_t)m * D_ + n0;
                    const float* bsp = bias + n0;
                    float2 o; o.x = vx + bsp[c]; o.y = vy + bsp[c + 1];
                    *(float2*)(dst + c) = o;
                }
            }
        }
    }
}

// ---------------------------------------------------------------------------
// fp16 tensor-core causal flash attention, warp-decoupled.
// Per-tile-slot mbarriers with cp.async.mbarrier.arrive.NOINC (the non-noinc
// form self-increments expect-count and can never complete -> R10 deadlock).
// CTA barrier every 2nd tile bounds warp drift <= 1 iter (ring-alias proof
// in R10 notes). K ring 4, V ring 5, prefetch distance 2.
// ---------------------------------------------------------------------------
#define BM 128
#define BK 64
#define KSTH (64 * 72)     // K or V tile (halves)
#define PSTH (128 * 72)    // Q/P buffer (halves)
#define KRING 4
#define VRING 5

__global__ __launch_bounds__(256, 1) void attn_mma_kernel()
{
    extern __shared__ __half smh[];
    const uint32_t sb  = smem_u32(smh);
    const uint32_t uMb = sb;                         // 4 mbarriers (8B each)
    const uint32_t uKb = sb + 64;                    // [KRING][KSTH]
    const uint32_t uVb = uKb + KRING * KSTH * 2;     // [VRING][KSTH]
    const uint32_t uPq = uVb + VRING * KSTH * 2;     // [2][PSTH] (buf0 = Q stage)
    __half* Pq = smh + (64 + (KRING + VRING) * KSTH * 2) / 2;

    const int qi  = (int)(gridDim.x - 1 - blockIdx.x);  // heavy tiles first
    const int h   = blockIdx.y, b = blockIdx.z;
    const int tid = threadIdx.x;
    const int w   = tid >> 5, lane = tid & 31;
    const int grp = lane >> 2, tig = lane & 3;
    const int m0  = qi * BM;
    const size_t base = ((size_t)b * H_ + h) * N_ * E3_;

    const int lrA = ((lane >> 3) & 1) * 8 + (lane & 7);
    const int lcA = ((lane >> 4) & 1) * 8;
    const int lrB = ((lane >> 4) & 1) * 8 + (lane & 7);
    const int lcB = ((lane >> 3) & 1) * 8;

    const int nt = (m0 + BM) / BK;

    if (tid < KRING) {
        asm volatile("mbarrier.init.shared.b64 [%0], 256;"
                     :: "r"(uMb + (uint32_t)(tid * 8)) : "memory");
    }
    __syncthreads();

    auto load_kv = [&](int kt) {
        const __half* kp = g_kqv + base + (size_t)(kt * BK) * E3_;
        const uint32_t kd = uKb + (uint32_t)(kt % KRING) * KSTH * 2;
#pragma unroll
        for (int j = 0; j < 2; ++j) {
            const int i = tid + j * 256;
            const int n = i >> 3, c = (i & 7) << 3;
            cpa16(kd + (uint32_t)(n * 72 + c) * 2, kp + (size_t)n * E3_ + c);
        }
        const __half* vp = kp + 2 * HD_;
        const uint32_t vd = uVb + (uint32_t)(kt % VRING) * KSTH * 2;
#pragma unroll
        for (int j = 0; j < 2; ++j) {
            const int i = tid + j * 256;
            const int n = i >> 3, c = (i & 7) << 3;
            cpa16(vd + (uint32_t)(n * 72 + c) * 2, vp + (size_t)n * E3_ + c);
        }
        asm volatile("cp.async.mbarrier.arrive.noinc.shared.b64 [%0];"
                     :: "r"(uMb + (uint32_t)((kt % KRING) * 8)) : "memory");
    };

    // Stage Q (128 x 64 halves) into Pq buffer 0, plus tiles 0,1
    {
        const __half* q0 = g_kqv + base + (size_t)m0 * E3_ + HD_;
#pragma unroll
        for (int j = 0; j < 4; ++j) {
            const int i = tid + j * 256;
            const int r = i >> 3, c = (i & 7) << 3;
            cpa16(uPq + (uint32_t)(r * 72 + c) * 2, q0 + (size_t)r * E3_ + c);
        }
    }
    load_kv(0);
    if (1 < nt) load_kv(1);
    asm volatile("cp.async.commit_group;" ::: "memory");
    asm volatile("cp.async.wait_group 0;" ::: "memory");
    __syncthreads();   // all warps' Q slices visible

    // Q fragments (unscaled) in registers for the whole kernel
    uint32_t qf[4][4];
    {
        const uint32_t uQw = uPq + (uint32_t)((w * 16 + lrA) * 72) * 2;
#pragma unroll
        for (int ks = 0; ks < 4; ++ks)
            ldsm4(qf[ks], uQw + (uint32_t)(ks * 16 + lcA) * 2);
    }
    __syncthreads();   // Q consumed before P[0] writes at iter 0

    const int r0    = m0 + w * 16 + grp;
    const int r1    = r0 + 8;
    const int rmax  = m0 + w * 16 + 15;
    const int diag0 = m0 / BK;

    float oacc[8][4];
#pragma unroll
    for (int ni = 0; ni < 8; ++ni)
#pragma unroll
        for (int r = 0; r < 4; ++r) oacc[ni][r] = 0.f;
    float mr0 = NEG_INF, mr1 = NEG_INF, l0 = 0.f, l1 = 0.f;

    for (int kt = 0; kt < nt; ++kt) {
        if ((kt & 1) == 0) __syncthreads();   // bound warp drift <= 1 iter
        if (kt + 2 < nt) load_kv(kt + 2);
        mbar_wait(uMb + (uint32_t)((kt % KRING) * 8), (uint32_t)((kt >> 2) & 1));

        const bool cur  = (kt * BK <= rmax);
        const bool prev = (kt > 0) && ((kt - 1) * BK <= rmax);

        float s[8][4];
        if (cur) {
            const uint32_t uKp = uKb + (uint32_t)(kt % KRING) * KSTH * 2;
#pragma unroll
            for (int ni = 0; ni < 8; ++ni)
#pragma unroll
                for (int r = 0; r < 4; ++r) s[ni][r] = 0.f;
#pragma unroll
            for (int ks = 0; ks < 4; ++ks) {
                const int k = ks * 16;
                uint32_t bf[8][2];
#pragma unroll
                for (int np = 0; np < 4; ++np) {
                    uint32_t r[4];
                    ldsm4(r, uKp + (uint32_t)((np * 16 + lrB) * 72 + k + lcB) * 2);
                    bf[2 * np][0] = r[0]; bf[2 * np][1] = r[1];
                    bf[2 * np + 1][0] = r[2]; bf[2 * np + 1][1] = r[3];
                }
#pragma unroll
                for (int ni = 0; ni < 8; ++ni)
                    mma_f16(s[ni], qf[ks], bf[ni]);
            }
        }

        // Deferred PV for tile kt-1
        if (prev) {
            const uint32_t uVp = uVb + (uint32_t)((kt - 1) % VRING) * KSTH * 2;
            const uint32_t uPp = uPq + (uint32_t)((kt - 1) & 1) * PSTH * 2
                               + (uint32_t)((w * 16 + lrA) * 72) * 2;
#pragma unroll
            for (int ks = 0; ks < 4; ++ks) {
                const int k = ks * 16;
                uint32_t a[4];
                ldsm4(a, uPp + (uint32_t)(k + lcA) * 2);
                uint32_t bf[8][2];
#pragma unroll
                for (int np = 0; np < 4; ++np) {
                    uint32_t r[4];
                    ldsm4t(r, uVp + (uint32_t)((k + lrA) * 72 + np * 16 + lcA) * 2);
                    bf[2 * np][0] = r[0]; bf[2 * np][1] = r[1];
                    bf[2 * np + 1][0] = r[2]; bf[2 * np + 1][1] = r[3];
                }
#pragma unroll
                for (int ni = 0; ni < 8; ++ni)
                    mma_f16(oacc[ni], a, bf[ni]);
            }
        }

        if (cur) {
            if (kt >= diag0) {
                const int colb = kt * BK;
#pragma unroll
                for (int ni = 0; ni < 8; ++ni) {
                    const int c = colb + ni * 8 + 2 * tig;
                    if (c > r0)     s[ni][0] = NEG_INF;
                    if (c + 1 > r0) s[ni][1] = NEG_INF;
                    if (c > r1)     s[ni][2] = NEG_INF;
                    if (c + 1 > r1) s[ni][3] = NEG_INF;
                }
            }

            float mx0 = NEG_INF, mx1 = NEG_INF;
#pragma unroll
            for (int ni = 0; ni < 8; ++ni) {
                mx0 = fmaxf(mx0, fmaxf(s[ni][0], s[ni][1]));
                mx1 = fmaxf(mx1, fmaxf(s[ni][2], s[ni][3]));
            }
            mx0 = fmaxf(mx0, __shfl_xor_sync(0xffffffffu, mx0, 1));
            mx0 = fmaxf(mx0, __shfl_xor_sync(0xffffffffu, mx0, 2));
            mx1 = fmaxf(mx1, __shfl_xor_sync(0xffffffffu, mx1, 1));
            mx1 = fmaxf(mx1, __shfl_xor_sync(0xffffffffu, mx1, 2));

            const float mn0 = fmaxf(mr0, mx0 * QSCALE);
            const float mn1 = fmaxf(mr1, mx1 * QSCALE);
            const float a0 = ex2(mr0 - mn0), a1 = ex2(mr1 - mn1);
            float sum0 = 0.f, sum1 = 0.f;
#pragma unroll
            for (int ni = 0; ni < 8; ++ni) {
                s[ni][0] = ex2(fmaf(s[ni][0], QSCALE, -mn0));
                s[ni][1] = ex2(fmaf(s[ni][1], QSCALE, -mn0));
                s[ni][2] = ex2(fmaf(s[ni][2], QSCALE, -mn1));
                s[ni][3] = ex2(fmaf(s[ni][3], QSCALE, -mn1));
                sum0 += s[ni][0] + s[ni][1];
                sum1 += s[ni][2] + s[ni][3];
            }
            sum0 += __shfl_xor_sync(0xffffffffu, sum0, 1);
            sum0 += __shfl_xor_sync(0xffffffffu, sum0, 2);
            sum1 += __shfl_xor_sync(0xffffffffu, sum1, 1);
            sum1 += __shfl_xor_sync(0xffffffffu, sum1, 2);

            l0 = l0 * a0 + sum0;  mr0 = mn0;
            l1 = l1 * a1 + sum1;  mr1 = mn1;
#pragma unroll
            for (int ni = 0; ni < 8; ++ni) {
                oacc[ni][0] *= a0; oacc[ni][1] *= a0;
                oacc[ni][2] *= a1; oacc[ni][3] *= a1;
            }

            // Store P (fp16) into this warp's private strip, parity kt&1
            __half* prow0 = Pq + (kt & 1) * PSTH + (w * 16 + grp) * 72;
            __half* prow1 = prow0 + 8 * 72;
#pragma unroll
            for (int ni = 0; ni < 8; ++ni) {
                const int c = ni * 8 + 2 * tig;
                *(__half2*)(prow0 + c) = __floats2half2_rn(s[ni][0], s[ni][1]);
                *(__half2*)(prow1 + c) = __floats2half2_rn(s[ni][2], s[ni][3]);
            }
            __syncwarp();
        }
    }

    // Tail PV for the last tile
    if ((nt - 1) * BK <= rmax) {
        const int kt = nt - 1;
        const uint32_t uVp = uVb + (uint32_t)(kt % VRING) * KSTH * 2;
        const uint32_t uPp = uPq + (uint32_t)(kt & 1) * PSTH * 2
                           + (uint32_t)((w * 16 + lrA) * 72) * 2;
#pragma unroll
        for (int ks = 0; ks < 4; ++ks) {
            const int k = ks * 16;
            uint32_t a[4];
            ldsm4(a, uPp + (uint32_t)(k + lcA) * 2);
            uint32_t bf[8][2];
#pragma unroll
            for (int np = 0; np < 4; ++np) {
                uint32_t r[4];
                ldsm4t(r, uVp + (uint32_t)((k + lrA) * 72 + np * 16 + lcA) * 2);
                bf[2 * np][0] = r[0]; bf[2 * np][1] = r[1];
                bf[2 * np + 1][0] = r[2]; bf[2 * np + 1][1] = r[3];
            }
#pragma unroll
            for (int ni = 0; ni < 8; ++ni)
                mma_f16(oacc[ni], a, bf[ni]);
        }
    }

    // Epilogue: normalize, fp16-store (proj GEMM consumes g_sa)
    const float inv0 = 1.0f / l0, inv1 = 1.0f / l1;
    __half* d0 = g_sa + ((size_t)b * N_ + r0) * D_ + h * HD_;
    __half* d1 = g_sa + ((size_t)b * N_ + r1) * D_ + h * HD_;
#pragma unroll
    for (int ni = 0; ni < 8; ++ni) {
        const int c = ni * 8 + 2 * tig;
        *(__half2*)(d0 + c) = __floats2half2_rn(oacc[ni][0] * inv0, oacc[ni][1] * inv0);
        *(__half2*)(d1 + c) = __floats2half2_rn(oacc[ni][2] * inv1, oacc[ni][3] * inv1);
    }
}

// ---------------------------------------------------------------------------
extern "C" void kernel_launch(void* const* d_in, const int* in_sizes, int n_in,
                              void* d_out, int out_size)
{
    const float* x      = (const float*)d_in[0];
    const float* W_kqv  = (const float*)d_in[1];
    const float* b_kqv  = (const float*)d_in[2];
    const float* W_proj = (const float*)d_in[3];
    const float* b_proj = (const float*)d_in[4];
    float* out = (float*)d_out;

    const int SMEM_Q = 3 * (128 + E3_) * 72 * 2;                 // 138240
    const int SMEM_P = 3 * (128 + 128) * 72 * 2;                 // 110592
    const int SMEM_A = 64 + ((KRING + VRING) * KSTH + 2 * PSTH) * 2;  // 202816
    cudaFuncSetAttribute(gemm_mma_kernel<E3_, 1>,
                         cudaFuncAttributeMaxDynamicSharedMemorySize, SMEM_Q);
    cudaFuncSetAttribute(gemm_mma_kernel<128, 0>,
                         cudaFuncAttributeMaxDynamicSharedMemorySize, SMEM_P);
    cudaFuncSetAttribute(attn_mma_kernel,
                         cudaFuncAttributeMaxDynamicSharedMemorySize, SMEM_A);

    prep_kernel<<<PREP_X + PREP_KQV + PREP_PRJ, 256>>>(x, W_kqv, W_proj);

    gemm_mma_kernel<E3_, 1><<<dim3(MROWS / 128, H_), 256, SMEM_Q>>>(b_kqv, nullptr);
    attn_mma_kernel<<<dim3(N_ / BM, H_, B_), 256, SMEM_A>>>();
    gemm_mma_kernel<128, 0><<<dim3(MROWS / 128, D_ / 128), 256, SMEM_P>>>(b_proj, out);
}